// round 1
// baseline (speedup 1.0000x reference)
#include <cuda_runtime.h>
#include <math.h>

#define S_   4096
#define E_   128
#define H_   256
#define NE_  4
#define NH_  4
#define HD_  64
#define FF_  2048
#define NL_  2
#define V_   10000
#define EPS_ 1e-5f
#define SCALE_ 0.125f   /* 1/sqrt(64) */

// ---------------- scratch (device globals; allocation-free) ----------------
__device__ float g_h  [S_ * H_];
__device__ float g_y  [S_ * H_];
__device__ float g_e0 [S_ * H_];
__device__ float g_e1 [S_ * H_];
__device__ float g_qkv[S_ * 3 * H_];
__device__ float g_a  [S_ * H_];
__device__ float g_ff [S_ * FF_];
__device__ float g_att[67108864];   // 4 * 4096 * 4096 fp32 = 268 MB
__device__ float g_vals[S_ * 2];
__device__ int   g_sel[2];

// ---------------- embed gather ----------------
__global__ void embed_kernel(const int* __restrict__ x, const float* __restrict__ emb,
                             float* __restrict__ out) {
    int s = blockIdx.x;
    int d = threadIdx.x;           // E_ = 128 threads
    out[s * E_ + d] = emb[(long)x[s] * E_ + d];
}

// ---------------- MoE gate: softmax over NE=4, per-token top2 vals, token0 sel ----------------
__global__ void gate_kernel(const float* __restrict__ x, int din,
                            const float* __restrict__ gw, const float* __restrict__ gb,
                            float* __restrict__ vals, int* __restrict__ sel) {
    int gtid = blockIdx.x * blockDim.x + threadIdx.x;
    int tok  = gtid >> 5;
    int lane = gtid & 31;
    if (tok >= S_) return;
    const float* xr = x + (long)tok * din;
    float p0 = 0.f, p1 = 0.f, p2 = 0.f, p3 = 0.f;
    for (int d = lane; d < din; d += 32) {
        float xv = xr[d];
        p0 += xv * gw[0 * din + d];
        p1 += xv * gw[1 * din + d];
        p2 += xv * gw[2 * din + d];
        p3 += xv * gw[3 * din + d];
    }
    #pragma unroll
    for (int o = 16; o > 0; o >>= 1) {
        p0 += __shfl_xor_sync(0xffffffffu, p0, o);
        p1 += __shfl_xor_sync(0xffffffffu, p1, o);
        p2 += __shfl_xor_sync(0xffffffffu, p2, o);
        p3 += __shfl_xor_sync(0xffffffffu, p3, o);
    }
    if (lane == 0) {
        float sc[4] = { p0 + gb[0], p1 + gb[1], p2 + gb[2], p3 + gb[3] };
        float m = fmaxf(fmaxf(sc[0], sc[1]), fmaxf(sc[2], sc[3]));
        float e[4]; float sum = 0.f;
        #pragma unroll
        for (int i = 0; i < 4; i++) { e[i] = expf(sc[i] - m); sum += e[i]; }
        float inv = 1.f / sum;
        #pragma unroll
        for (int i = 0; i < 4; i++) e[i] *= inv;
        int i0 = 0;
        #pragma unroll
        for (int i = 1; i < 4; i++) if (e[i] > e[i0]) i0 = i;
        int i1 = -1;
        #pragma unroll
        for (int i = 0; i < 4; i++) {
            if (i == i0) continue;
            if (i1 < 0 || e[i] > e[i1]) i1 = i;
        }
        vals[tok * 2 + 0] = e[i0];
        vals[tok * 2 + 1] = e[i1];
        if (tok == 0) { sel[0] = i0; sel[1] = i1; }
    }
}

// ---------------- MoE combine: y = v0*(e0+eb[sel0]) + v1*(e1+eb[sel1]) ----------------
__global__ void moe_combine(const float* __restrict__ e0, const float* __restrict__ e1,
                            const float* __restrict__ eb, const float* __restrict__ vals,
                            const int* __restrict__ sel, float* __restrict__ out) {
    long i = (long)blockIdx.x * blockDim.x + threadIdx.x;
    if (i >= (long)S_ * H_) return;
    int s = (int)(i / H_);
    int h = (int)(i % H_);
    float b0 = eb[sel[0] * H_ + h];
    float b1 = eb[sel[1] * H_ + h];
    out[i] = vals[s * 2] * (e0[i] + b0) + vals[s * 2 + 1] * (e1[i] + b1);
}

// ---------------- generic register-tiled GEMM: C = alpha * A(MxK) * B^eff + bias ----------------
// A element (m,k) at A[m*as_m + k]          (as_k == 1 always in this net)
// B element (n,k) at B[n*bs_n + k*bs_k]
// Optional device-side expert indirection: B += sel[selk]*selStride
template <int BM, int BN, int BK, int TM, int TN>
__global__ void gemm_kernel(const float* __restrict__ A, const float* __restrict__ B,
                            const float* __restrict__ bias, float* __restrict__ C,
                            int M, int N, int K,
                            int as_m, int bs_n, int bs_k, int ldc,
                            long batchA, long batchB, long batchC,
                            float alpha, int do_relu,
                            const int* __restrict__ sel, int selk, long selStride) {
    constexpr int TX = BN / TN;            // 16
    constexpr int TY = BM / TM;            // 16
    constexpr int THREADS = TX * TY;       // 256
    __shared__ float As[BK][BM + 1];
    __shared__ float Bs[BK][BN + 1];

    A += (long)blockIdx.z * batchA;
    B += (long)blockIdx.z * batchB;
    C += (long)blockIdx.z * batchC;
    if (sel) B += (long)sel[selk] * selStride;

    int bm = blockIdx.y * BM;
    int bn = blockIdx.x * BN;
    int tid = threadIdx.x;
    int tx = tid % TX;
    int ty = tid / TX;

    float acc[TM][TN];
    #pragma unroll
    for (int i = 0; i < TM; i++)
        #pragma unroll
        for (int j = 0; j < TN; j++) acc[i][j] = 0.f;

    for (int k0 = 0; k0 < K; k0 += BK) {
        // A tile: kk-fastest (as_k==1 -> coalesced)
        #pragma unroll
        for (int i = tid; i < BM * BK; i += THREADS) {
            int kk = i % BK, r = i / BK;
            int gm = bm + r;
            As[kk][r] = (gm < M) ? A[(long)gm * as_m + (k0 + kk)] : 0.f;
        }
        // B tile: pick load order matching contiguity
        if (bs_k == 1) {
            #pragma unroll
            for (int i = tid; i < BN * BK; i += THREADS) {
                int kk = i % BK, c = i / BK;
                int gn = bn + c;
                Bs[kk][c] = (gn < N) ? B[(long)gn * bs_n + (k0 + kk)] : 0.f;
            }
        } else {
            #pragma unroll
            for (int i = tid; i < BN * BK; i += THREADS) {
                int c = i % BN, kk = i / BN;
                int gn = bn + c;
                Bs[kk][c] = (gn < N) ? B[(long)gn * bs_n + (long)(k0 + kk) * bs_k] : 0.f;
            }
        }
        __syncthreads();

        #pragma unroll
        for (int kk = 0; kk < BK; kk++) {
            float a[TM], b[TN];
            #pragma unroll
            for (int i = 0; i < TM; i++) a[i] = As[kk][ty * TM + i];
            #pragma unroll
            for (int j = 0; j < TN; j++) b[j] = Bs[kk][tx * TN + j];
            #pragma unroll
            for (int i = 0; i < TM; i++)
                #pragma unroll
                for (int j = 0; j < TN; j++) acc[i][j] += a[i] * b[j];
        }
        __syncthreads();
    }

    #pragma unroll
    for (int i = 0; i < TM; i++) {
        int gm = bm + ty * TM + i;
        if (gm >= M) continue;
        #pragma unroll
        for (int j = 0; j < TN; j++) {
            int gn = bn + tx * TN + j;
            if (gn >= N) continue;
            float v = acc[i][j] * alpha;
            if (bias) v += bias[gn];
            if (do_relu) v = fmaxf(v, 0.f);
            C[(long)gm * ldc + gn] = v;
        }
    }
}

// ---------------- residual add + LayerNorm (in place on h) ----------------
__global__ void ln_kernel(float* __restrict__ h, const float* __restrict__ t,
                          const float* __restrict__ g, const float* __restrict__ b) {
    __shared__ float red[H_];
    int s = blockIdx.x;
    int d = threadIdx.x;           // H_ = 256 threads
    float v = h[s * H_ + d] + t[s * H_ + d];
    red[d] = v;
    __syncthreads();
    for (int o = H_ / 2; o > 0; o >>= 1) {
        if (d < o) red[d] += red[d + o];
        __syncthreads();
    }
    float m = red[0] * (1.f / H_);
    __syncthreads();
    float c = v - m;
    red[d] = c * c;
    __syncthreads();
    for (int o = H_ / 2; o > 0; o >>= 1) {
        if (d < o) red[d] += red[d + o];
        __syncthreads();
    }
    float var = red[0] * (1.f / H_);
    h[s * H_ + d] = c * rsqrtf(var + EPS_) * g[d] + b[d];
}

// ---------------- row softmax over attention scores (row len 4096) ----------------
__global__ void softmax_kernel(float* __restrict__ att) {
    __shared__ float red[256];
    float* p = att + (long)blockIdx.x * S_;
    int t = threadIdx.x;
    float loc[16];
    float m = -1e30f;
    #pragma unroll
    for (int i = 0; i < 16; i++) {
        loc[i] = p[t + i * 256];
        m = fmaxf(m, loc[i]);
    }
    red[t] = m;
    __syncthreads();
    for (int o = 128; o > 0; o >>= 1) {
        if (t < o) red[t] = fmaxf(red[t], red[t + o]);
        __syncthreads();
    }
    m = red[0];
    __syncthreads();
    float sum = 0.f;
    #pragma unroll
    for (int i = 0; i < 16; i++) {
        loc[i] = expf(loc[i] - m);
        sum += loc[i];
    }
    red[t] = sum;
    __syncthreads();
    for (int o = 128; o > 0; o >>= 1) {
        if (t < o) red[t] += red[t + o];
        __syncthreads();
    }
    float inv = 1.f / red[0];
    #pragma unroll
    for (int i = 0; i < 16; i++) p[t + i * 256] = loc[i] * inv;
}

// ---------------- final log_softmax over vocab rows (len 10000), in place ----------------
__global__ void logsoftmax_kernel(float* __restrict__ out) {
    __shared__ float red[256];
    float* p = out + (long)blockIdx.x * V_;
    int t = threadIdx.x;
    float loc[40];
    float m = -1e30f;
    #pragma unroll
    for (int i = 0; i < 40; i++) {
        int c = t + i * 256;
        loc[i] = (c < V_) ? p[c] : -1e30f;
        m = fmaxf(m, loc[i]);
    }
    red[t] = m;
    __syncthreads();
    for (int o = 128; o > 0; o >>= 1) {
        if (t < o) red[t] = fmaxf(red[t], red[t + o]);
        __syncthreads();
    }
    m = red[0];
    __syncthreads();
    float sum = 0.f;
    #pragma unroll
    for (int i = 0; i < 40; i++) {
        int c = t + i * 256;
        if (c < V_) sum += expf(loc[i] - m);
    }
    red[t] = sum;
    __syncthreads();
    for (int o = 128; o > 0; o >>= 1) {
        if (t < o) red[t] += red[t + o];
        __syncthreads();
    }
    float lse = m + logf(red[0]);
    #pragma unroll
    for (int i = 0; i < 40; i++) {
        int c = t + i * 256;
        if (c < V_) p[c] = loc[i] - lse;
    }
}

// ---------------- host side ----------------
static inline void gemm(const float* A, const float* B, const float* bias, float* C,
                        int M, int N, int K,
                        int as_m, int bs_n, int bs_k, int ldc,
                        long bA, long bB, long bC, int Z,
                        float alpha, int relu,
                        const int* sel = nullptr, int selk = 0, long selStride = 0) {
    dim3 grid((N + 63) / 64, (M + 63) / 64, Z);
    gemm_kernel<64, 64, 16, 4, 4><<<grid, 256>>>(A, B, bias, C, M, N, K,
                                                 as_m, bs_n, bs_k, ldc,
                                                 bA, bB, bC, alpha, relu,
                                                 sel, selk, selStride);
}

extern "C" void kernel_launch(void* const* d_in, const int* in_sizes, int n_in,
                              void* d_out, int out_size) {
    const int*   x         = (const int*)d_in[0];
    const float* emb       = (const float*)d_in[1];
    const float* moe_gw[3] = { (const float*)d_in[2], (const float*)d_in[6], (const float*)d_in[10] };
    const float* moe_gb[3] = { (const float*)d_in[3], (const float*)d_in[7], (const float*)d_in[11] };
    const float* moe_ew[3] = { (const float*)d_in[4], (const float*)d_in[8], (const float*)d_in[12] };
    const float* moe_eb[3] = { (const float*)d_in[5], (const float*)d_in[9], (const float*)d_in[13] };
    const float* attn_in_w  = (const float*)d_in[14];
    const float* attn_in_b  = (const float*)d_in[15];
    const float* attn_out_w = (const float*)d_in[16];
    const float* attn_out_b = (const float*)d_in[17];
    const float* ln1_g = (const float*)d_in[18];
    const float* ln1_b = (const float*)d_in[19];
    const float* ln2_g = (const float*)d_in[20];
    const float* ln2_b = (const float*)d_in[21];
    const float* ff1_w = (const float*)d_in[22];
    const float* ff1_b = (const float*)d_in[23];
    const float* ff2_w = (const float*)d_in[24];
    const float* ff2_b = (const float*)d_in[25];
    const float* fc_w  = (const float*)d_in[26];
    const float* fc_b  = (const float*)d_in[27];
    const float* out_w = (const float*)d_in[28];
    const float* out_b = (const float*)d_in[29];
    float* out = (float*)d_out;

    float *hbuf, *ybuf, *e0, *e1, *qkv, *abuf, *ffbuf, *att, *vals;
    int* sel;
    cudaGetSymbolAddress((void**)&hbuf,  g_h);
    cudaGetSymbolAddress((void**)&ybuf,  g_y);
    cudaGetSymbolAddress((void**)&e0,    g_e0);
    cudaGetSymbolAddress((void**)&e1,    g_e1);
    cudaGetSymbolAddress((void**)&qkv,   g_qkv);
    cudaGetSymbolAddress((void**)&abuf,  g_a);
    cudaGetSymbolAddress((void**)&ffbuf, g_ff);
    cudaGetSymbolAddress((void**)&att,   g_att);
    cudaGetSymbolAddress((void**)&vals,  g_vals);
    cudaGetSymbolAddress((void**)&sel,   g_sel);

    // 1) embedding gather -> hbuf [S, E]
    embed_kernel<<<S_, E_>>>(x, emb, hbuf);

    // 2) three MoE blocks; ping-pong hbuf/ybuf
    const float* moe_in[3] = { hbuf, ybuf, hbuf };
    float*       moe_out_p[3] = { ybuf, hbuf, ybuf };
    int          moe_din[3] = { E_, H_, H_ };
    for (int i = 0; i < 3; i++) {
        int din = moe_din[i];
        gate_kernel<<<(S_ * 32) / 256, 256>>>(moe_in[i], din, moe_gw[i], moe_gb[i], vals, sel);
        // expert k GEMMs: [S,din] x ew[sel[k]]^T (ew row n has din contiguous) -> [S, H]
        gemm(moe_in[i], moe_ew[i], nullptr, e0, S_, H_, din, din, din, 1, H_,
             0, 0, 0, 1, 1.f, 0, sel, 0, (long)H_ * din);
        gemm(moe_in[i], moe_ew[i], nullptr, e1, S_, H_, din, din, din, 1, H_,
             0, 0, 0, 1, 1.f, 0, sel, 1, (long)H_ * din);
        moe_combine<<<(S_ * H_) / 256, 256>>>(e0, e1, moe_eb[i], vals, sel, moe_out_p[i]);
    }
    float* cur = ybuf;   // after moe2

    // 3) transformer layers
    for (int l = 0; l < NL_; l++) {
        // qkv projection: [S,H] -> [S,3H]
        gemm(cur, attn_in_w + (long)l * 3 * H_ * H_, attn_in_b + (long)l * 3 * H_,
             qkv, S_, 3 * H_, H_, H_, H_, 1, 3 * H_, 0, 0, 0, 1, 1.f, 0);
        // scores per head: q @ k^T * SCALE  -> att [NH, S, S]
        gemm(qkv, qkv + H_, nullptr, att, S_, S_, HD_,
             3 * H_, 3 * H_, 1, S_,
             HD_, HD_, (long)S_ * S_, NH_, SCALE_, 0);
        softmax_kernel<<<NH_ * S_, 256>>>(att);
        // AV per head: att @ v -> abuf[S, H] (head h occupies cols h*64..)
        gemm(att, qkv + 2 * H_, nullptr, abuf, S_, HD_, S_,
             S_, 1, 3 * H_, H_,
             (long)S_ * S_, HD_, HD_, NH_, 1.f, 0);
        // output projection
        gemm(abuf, attn_out_w + (long)l * H_ * H_, attn_out_b + (long)l * H_,
             e0, S_, H_, H_, H_, H_, 1, H_, 0, 0, 0, 1, 1.f, 0);
        ln_kernel<<<S_, H_>>>(cur, e0, ln1_g + l * H_, ln1_b + l * H_);
        // FF
        gemm(cur, ff1_w + (long)l * FF_ * H_, ff1_b + (long)l * FF_,
             ffbuf, S_, FF_, H_, H_, H_, 1, FF_, 0, 0, 0, 1, 1.f, 1);
        gemm(ffbuf, ff2_w + (long)l * H_ * FF_, ff2_b + (long)l * H_,
             e0, S_, H_, FF_, FF_, FF_, 1, H_, 0, 0, 0, 1, 1.f, 0);
        ln_kernel<<<S_, H_>>>(cur, e0, ln2_g + l * H_, ln2_b + l * H_);
    }

    // 4) fc + vocab logits + log_softmax
    gemm(cur, fc_w, fc_b, e0, S_, H_, H_, H_, H_, 1, H_, 0, 0, 0, 1, 1.f, 0);
    gemm(e0, out_w, out_b, out, S_, V_, H_, H_, H_, 1, V_, 0, 0, 0, 1, 1.f, 0);
    logsoftmax_kernel<<<S_, 256>>>(out);
}

// round 2
// speedup vs baseline: 4.0456x; 4.0456x over previous
#include <cuda_runtime.h>
#include <cuda_bf16.h>
#include <math.h>

#define S_   4096
#define E_   128
#define H_   256
#define NE_  4
#define NH_  4
#define HD_  64
#define FF_  2048
#define NL_  2
#define V_   10000
#define EPS_ 1e-5f
#define SCALE_ 0.125f   /* 1/sqrt(64) */

// ---------------- scratch (device globals; allocation-free) ----------------
__device__ float g_h  [S_ * H_];
__device__ float g_y  [S_ * H_];
__device__ float g_e0 [S_ * H_];
__device__ float g_e1 [S_ * H_];
__device__ float g_qkv[S_ * 3 * H_];
__device__ float g_a  [S_ * H_];
__device__ float g_ff [S_ * FF_];
__device__ float g_att[67108864];   // 4 * 4096 * 4096 fp32 = 268 MB
__device__ float g_vals[S_ * 2];
__device__ int   g_sel[2];

// ---------------- embed gather ----------------
__global__ void embed_kernel(const int* __restrict__ x, const float* __restrict__ emb,
                             float* __restrict__ out) {
    int s = blockIdx.x;
    int d = threadIdx.x;           // E_ = 128 threads
    out[s * E_ + d] = emb[(long)x[s] * E_ + d];
}

// ---------------- MoE gate ----------------
__global__ void gate_kernel(const float* __restrict__ x, int din,
                            const float* __restrict__ gw, const float* __restrict__ gb,
                            float* __restrict__ vals, int* __restrict__ sel) {
    int gtid = blockIdx.x * blockDim.x + threadIdx.x;
    int tok  = gtid >> 5;
    int lane = gtid & 31;
    if (tok >= S_) return;
    const float* xr = x + (long)tok * din;
    float p0 = 0.f, p1 = 0.f, p2 = 0.f, p3 = 0.f;
    for (int d = lane; d < din; d += 32) {
        float xv = xr[d];
        p0 += xv * gw[0 * din + d];
        p1 += xv * gw[1 * din + d];
        p2 += xv * gw[2 * din + d];
        p3 += xv * gw[3 * din + d];
    }
    #pragma unroll
    for (int o = 16; o > 0; o >>= 1) {
        p0 += __shfl_xor_sync(0xffffffffu, p0, o);
        p1 += __shfl_xor_sync(0xffffffffu, p1, o);
        p2 += __shfl_xor_sync(0xffffffffu, p2, o);
        p3 += __shfl_xor_sync(0xffffffffu, p3, o);
    }
    if (lane == 0) {
        float sc[4] = { p0 + gb[0], p1 + gb[1], p2 + gb[2], p3 + gb[3] };
        float m = fmaxf(fmaxf(sc[0], sc[1]), fmaxf(sc[2], sc[3]));
        float e[4]; float sum = 0.f;
        #pragma unroll
        for (int i = 0; i < 4; i++) { e[i] = expf(sc[i] - m); sum += e[i]; }
        float inv = 1.f / sum;
        #pragma unroll
        for (int i = 0; i < 4; i++) e[i] *= inv;
        int i0 = 0;
        #pragma unroll
        for (int i = 1; i < 4; i++) if (e[i] > e[i0]) i0 = i;
        int i1 = -1;
        #pragma unroll
        for (int i = 0; i < 4; i++) {
            if (i == i0) continue;
            if (i1 < 0 || e[i] > e[i1]) i1 = i;
        }
        vals[tok * 2 + 0] = e[i0];
        vals[tok * 2 + 1] = e[i1];
        if (tok == 0) { sel[0] = i0; sel[1] = i1; }
    }
}

// ---------------- MoE combine ----------------
__global__ void moe_combine(const float* __restrict__ e0, const float* __restrict__ e1,
                            const float* __restrict__ eb, const float* __restrict__ vals,
                            const int* __restrict__ sel, float* __restrict__ out) {
    long i = (long)blockIdx.x * blockDim.x + threadIdx.x;
    if (i >= (long)S_ * H_) return;
    int s = (int)(i / H_);
    int h = (int)(i % H_);
    float b0 = eb[sel[0] * H_ + h];
    float b1 = eb[sel[1] * H_ + h];
    out[i] = vals[s * 2] * (e0[i] + b0) + vals[s * 2 + 1] * (e1[i] + b1);
}

// ---------------- tensor-core GEMM (bf16 mma.sync, fp32 accum) ----------------
// C[M,N] = alpha * A * B(+bias)(+relu)
// A element (m,k) at A[m*as_m + k]   (k contiguous, always)
// B element (n,k) at B[n*bs_n + k*bs_k]
// Requires: M % 128 == 0, K % 32 == 0, N even. N guarded.
// BM=128, BN=64, BK=32, 256 threads (8 warps, 4x2).
__global__ __launch_bounds__(256)
void gemm_tc(const float* __restrict__ A, const float* __restrict__ B,
             const float* __restrict__ bias, float* __restrict__ C,
             int M, int N, int K,
             int as_m, int bs_n, int bs_k, int ldc,
             long batchA, long batchB, long batchC,
             float alpha, int do_relu,
             const int* __restrict__ sel, int selk, long selStride) {
    constexpr int BM = 128, BN = 64, BK = 32;
    constexpr int PAD = 8;                    // +16B row pad -> 20-bank stride, conflict-free frags
    __shared__ __align__(16) __nv_bfloat16 As[BM][BK + PAD];
    __shared__ __align__(16) __nv_bfloat16 Bs[BN][BK + PAD];

    A += (long)blockIdx.z * batchA;
    B += (long)blockIdx.z * batchB;
    C += (long)blockIdx.z * batchC;
    if (sel) B += (long)sel[selk] * selStride;

    int bm = blockIdx.y * BM;
    int bn = blockIdx.x * BN;
    int tid  = threadIdx.x;
    int lane = tid & 31;
    int wid  = tid >> 5;
    int warpM = (wid & 3) * 32;   // warp row offset within tile
    int warpN = (wid >> 2) * 32;  // warp col offset within tile

    float acc[2][4][4];
    #pragma unroll
    for (int mt = 0; mt < 2; mt++)
        #pragma unroll
        for (int nt = 0; nt < 4; nt++)
            #pragma unroll
            for (int r = 0; r < 4; r++) acc[mt][nt][r] = 0.f;

    int g = lane >> 2;            // 0..7
    int q = lane & 3;             // 0..3

    for (int k0 = 0; k0 < K; k0 += BK) {
        // --- load A tile: 128 rows x 32 k, float4 (8 per row), 4 per thread ---
        #pragma unroll
        for (int t = 0; t < 4; t++) {
            int idx = tid + t * 256;
            int row = idx >> 3;
            int kq  = idx & 7;
            const float4 v = *(const float4*)(A + (long)(bm + row) * as_m + k0 + kq * 4);
            __nv_bfloat162 p0 = __float22bfloat162_rn(make_float2(v.x, v.y));
            __nv_bfloat162 p1 = __float22bfloat162_rn(make_float2(v.z, v.w));
            *(__nv_bfloat162*)&As[row][kq * 4]     = p0;
            *(__nv_bfloat162*)&As[row][kq * 4 + 2] = p1;
        }
        // --- load B tile: 64 rows(n) x 32 k ---
        if (bs_k == 1) {
            #pragma unroll
            for (int t = 0; t < 2; t++) {
                int idx = tid + t * 256;
                int row = idx >> 3;
                int kq  = idx & 7;
                int gn  = bn + row;
                float4 v = make_float4(0.f, 0.f, 0.f, 0.f);
                if (gn < N) v = *(const float4*)(B + (long)gn * bs_n + k0 + kq * 4);
                __nv_bfloat162 p0 = __float22bfloat162_rn(make_float2(v.x, v.y));
                __nv_bfloat162 p1 = __float22bfloat162_rn(make_float2(v.z, v.w));
                *(__nv_bfloat162*)&Bs[row][kq * 4]     = p0;
                *(__nv_bfloat162*)&Bs[row][kq * 4 + 2] = p1;
            }
        } else {
            // n contiguous in gmem (bs_n==1 case: AV). Coalesce on n.
            #pragma unroll
            for (int t = 0; t < 8; t++) {
                int idx = tid + t * 256;
                int n = idx & 63;
                int k = idx >> 6;
                int gn = bn + n;
                float v = (gn < N) ? B[(long)gn * bs_n + (long)(k0 + k) * bs_k] : 0.f;
                Bs[n][k] = __float2bfloat16_rn(v);
            }
        }
        __syncthreads();

        #pragma unroll
        for (int ks = 0; ks < BK; ks += 16) {
            unsigned a[2][4], b[4][2];
            int ac = ks + q * 2;
            #pragma unroll
            for (int mt = 0; mt < 2; mt++) {
                int r = warpM + mt * 16 + g;
                a[mt][0] = *(const unsigned*)&As[r][ac];
                a[mt][1] = *(const unsigned*)&As[r + 8][ac];
                a[mt][2] = *(const unsigned*)&As[r][ac + 8];
                a[mt][3] = *(const unsigned*)&As[r + 8][ac + 8];
            }
            #pragma unroll
            for (int nt = 0; nt < 4; nt++) {
                int nr = warpN + nt * 8 + g;
                b[nt][0] = *(const unsigned*)&Bs[nr][ac];
                b[nt][1] = *(const unsigned*)&Bs[nr][ac + 8];
            }
            #pragma unroll
            for (int mt = 0; mt < 2; mt++)
                #pragma unroll
                for (int nt = 0; nt < 4; nt++) {
                    asm volatile(
                        "mma.sync.aligned.m16n8k16.row.col.f32.bf16.bf16.f32 "
                        "{%0,%1,%2,%3}, {%4,%5,%6,%7}, {%8,%9}, {%0,%1,%2,%3};\n"
                        : "+f"(acc[mt][nt][0]), "+f"(acc[mt][nt][1]),
                          "+f"(acc[mt][nt][2]), "+f"(acc[mt][nt][3])
                        : "r"(a[mt][0]), "r"(a[mt][1]), "r"(a[mt][2]), "r"(a[mt][3]),
                          "r"(b[nt][0]), "r"(b[nt][1]));
                }
        }
        __syncthreads();
    }

    // --- epilogue ---
    #pragma unroll
    for (int mt = 0; mt < 2; mt++) {
        int row0 = bm + warpM + mt * 16 + g;
        #pragma unroll
        for (int nt = 0; nt < 4; nt++) {
            int col = bn + warpN + nt * 8 + q * 2;
            if (col >= N) continue;      // N even -> col+1 also valid when col<N
            float b0 = bias ? bias[col]     : 0.f;
            float b1 = bias ? bias[col + 1] : 0.f;
            float v00 = acc[mt][nt][0] * alpha + b0;
            float v01 = acc[mt][nt][1] * alpha + b1;
            float v10 = acc[mt][nt][2] * alpha + b0;
            float v11 = acc[mt][nt][3] * alpha + b1;
            if (do_relu) {
                v00 = fmaxf(v00, 0.f); v01 = fmaxf(v01, 0.f);
                v10 = fmaxf(v10, 0.f); v11 = fmaxf(v11, 0.f);
            }
            *(float2*)(C + (long)row0 * ldc + col)       = make_float2(v00, v01);
            *(float2*)(C + (long)(row0 + 8) * ldc + col) = make_float2(v10, v11);
        }
    }
}

// ---------------- residual add + LayerNorm (in place on h) ----------------
__global__ void ln_kernel(float* __restrict__ h, const float* __restrict__ t,
                          const float* __restrict__ g, const float* __restrict__ b) {
    __shared__ float red[H_];
    int s = blockIdx.x;
    int d = threadIdx.x;           // H_ = 256 threads
    float v = h[s * H_ + d] + t[s * H_ + d];
    red[d] = v;
    __syncthreads();
    for (int o = H_ / 2; o > 0; o >>= 1) {
        if (d < o) red[d] += red[d + o];
        __syncthreads();
    }
    float m = red[0] * (1.f / H_);
    __syncthreads();
    float c = v - m;
    red[d] = c * c;
    __syncthreads();
    for (int o = H_ / 2; o > 0; o >>= 1) {
        if (d < o) red[d] += red[d + o];
        __syncthreads();
    }
    float var = red[0] * (1.f / H_);
    h[s * H_ + d] = c * rsqrtf(var + EPS_) * g[d] + b[d];
}

// ---------------- row softmax over attention scores (row len 4096) ----------------
__global__ void softmax_kernel(float* __restrict__ att) {
    __shared__ float red[256];
    float* p = att + (long)blockIdx.x * S_;
    int t = threadIdx.x;
    float loc[16];
    float m = -1e30f;
    #pragma unroll
    for (int i = 0; i < 16; i++) {
        loc[i] = p[t + i * 256];
        m = fmaxf(m, loc[i]);
    }
    red[t] = m;
    __syncthreads();
    for (int o = 128; o > 0; o >>= 1) {
        if (t < o) red[t] = fmaxf(red[t], red[t + o]);
        __syncthreads();
    }
    m = red[0];
    __syncthreads();
    float sum = 0.f;
    #pragma unroll
    for (int i = 0; i < 16; i++) {
        loc[i] = expf(loc[i] - m);
        sum += loc[i];
    }
    red[t] = sum;
    __syncthreads();
    for (int o = 128; o > 0; o >>= 1) {
        if (t < o) red[t] += red[t + o];
        __syncthreads();
    }
    float inv = 1.f / red[0];
    #pragma unroll
    for (int i = 0; i < 16; i++) p[t + i * 256] = loc[i] * inv;
}

// ---------------- final log_softmax over vocab rows (len 10000), in place ----------------
__global__ void logsoftmax_kernel(float* __restrict__ out) {
    __shared__ float red[256];
    float* p = out + (long)blockIdx.x * V_;
    int t = threadIdx.x;
    float loc[40];
    float m = -1e30f;
    #pragma unroll
    for (int i = 0; i < 40; i++) {
        int c = t + i * 256;
        loc[i] = (c < V_) ? p[c] : -1e30f;
        m = fmaxf(m, loc[i]);
    }
    red[t] = m;
    __syncthreads();
    for (int o = 128; o > 0; o >>= 1) {
        if (t < o) red[t] = fmaxf(red[t], red[t + o]);
        __syncthreads();
    }
    m = red[0];
    __syncthreads();
    float sum = 0.f;
    #pragma unroll
    for (int i = 0; i < 40; i++) {
        int c = t + i * 256;
        if (c < V_) sum += expf(loc[i] - m);
    }
    red[t] = sum;
    __syncthreads();
    for (int o = 128; o > 0; o >>= 1) {
        if (t < o) red[t] += red[t + o];
        __syncthreads();
    }
    float lse = m + logf(red[0]);
    #pragma unroll
    for (int i = 0; i < 40; i++) {
        int c = t + i * 256;
        if (c < V_) p[c] = loc[i] - lse;
    }
}

// ---------------- host side ----------------
static inline void gemm(const float* A, const float* B, const float* bias, float* C,
                        int M, int N, int K,
                        int as_m, int bs_n, int bs_k, int ldc,
                        long bA, long bB, long bC, int Z,
                        float alpha, int relu,
                        const int* sel = nullptr, int selk = 0, long selStride = 0) {
    dim3 grid((N + 63) / 64, M / 128, Z);
    gemm_tc<<<grid, 256>>>(A, B, bias, C, M, N, K,
                           as_m, bs_n, bs_k, ldc,
                           bA, bB, bC, alpha, relu,
                           sel, selk, selStride);
}

extern "C" void kernel_launch(void* const* d_in, const int* in_sizes, int n_in,
                              void* d_out, int out_size) {
    const int*   x         = (const int*)d_in[0];
    const float* emb       = (const float*)d_in[1];
    const float* moe_gw[3] = { (const float*)d_in[2], (const float*)d_in[6], (const float*)d_in[10] };
    const float* moe_gb[3] = { (const float*)d_in[3], (const float*)d_in[7], (const float*)d_in[11] };
    const float* moe_ew[3] = { (const float*)d_in[4], (const float*)d_in[8], (const float*)d_in[12] };
    const float* moe_eb[3] = { (const float*)d_in[5], (const float*)d_in[9], (const float*)d_in[13] };
    const float* attn_in_w  = (const float*)d_in[14];
    const float* attn_in_b  = (const float*)d_in[15];
    const float* attn_out_w = (const float*)d_in[16];
    const float* attn_out_b = (const float*)d_in[17];
    const float* ln1_g = (const float*)d_in[18];
    const float* ln1_b = (const float*)d_in[19];
    const float* ln2_g = (const float*)d_in[20];
    const float* ln2_b = (const float*)d_in[21];
    const float* ff1_w = (const float*)d_in[22];
    const float* ff1_b = (const float*)d_in[23];
    const float* ff2_w = (const float*)d_in[24];
    const float* ff2_b = (const float*)d_in[25];
    const float* fc_w  = (const float*)d_in[26];
    const float* fc_b  = (const float*)d_in[27];
    const float* out_w = (const float*)d_in[28];
    const float* out_b = (const float*)d_in[29];
    float* out = (float*)d_out;

    float *hbuf, *ybuf, *e0, *e1, *qkv, *abuf, *ffbuf, *att, *vals;
    int* sel;
    cudaGetSymbolAddress((void**)&hbuf,  g_h);
    cudaGetSymbolAddress((void**)&ybuf,  g_y);
    cudaGetSymbolAddress((void**)&e0,    g_e0);
    cudaGetSymbolAddress((void**)&e1,    g_e1);
    cudaGetSymbolAddress((void**)&qkv,   g_qkv);
    cudaGetSymbolAddress((void**)&abuf,  g_a);
    cudaGetSymbolAddress((void**)&ffbuf, g_ff);
    cudaGetSymbolAddress((void**)&att,   g_att);
    cudaGetSymbolAddress((void**)&vals,  g_vals);
    cudaGetSymbolAddress((void**)&sel,   g_sel);

    // 1) embedding gather -> hbuf [S, E]
    embed_kernel<<<S_, E_>>>(x, emb, hbuf);

    // 2) three MoE blocks; ping-pong hbuf/ybuf
    const float* moe_in[3] = { hbuf, ybuf, hbuf };
    float*       moe_out_p[3] = { ybuf, hbuf, ybuf };
    int          moe_din[3] = { E_, H_, H_ };
    for (int i = 0; i < 3; i++) {
        int din = moe_din[i];
        gate_kernel<<<(S_ * 32) / 256, 256>>>(moe_in[i], din, moe_gw[i], moe_gb[i], vals, sel);
        gemm(moe_in[i], moe_ew[i], nullptr, e0, S_, H_, din, din, din, 1, H_,
             0, 0, 0, 1, 1.f, 0, sel, 0, (long)H_ * din);
        gemm(moe_in[i], moe_ew[i], nullptr, e1, S_, H_, din, din, din, 1, H_,
             0, 0, 0, 1, 1.f, 0, sel, 1, (long)H_ * din);
        moe_combine<<<(S_ * H_) / 256, 256>>>(e0, e1, moe_eb[i], vals, sel, moe_out_p[i]);
    }
    float* cur = ybuf;   // after moe2

    // 3) transformer layers
    for (int l = 0; l < NL_; l++) {
        // qkv projection: [S,H] -> [S,3H]
        gemm(cur, attn_in_w + (long)l * 3 * H_ * H_, attn_in_b + (long)l * 3 * H_,
             qkv, S_, 3 * H_, H_, H_, H_, 1, 3 * H_, 0, 0, 0, 1, 1.f, 0);
        // scores per head: q @ k^T * SCALE  -> att [NH, S, S]
        gemm(qkv, qkv + H_, nullptr, att, S_, S_, HD_,
             3 * H_, 3 * H_, 1, S_,
             HD_, HD_, (long)S_ * S_, NH_, SCALE_, 0);
        softmax_kernel<<<NH_ * S_, 256>>>(att);
        // AV per head: att @ v -> abuf[S, H] (head h occupies cols h*64..)
        gemm(att, qkv + 2 * H_, nullptr, abuf, S_, HD_, S_,
             S_, 1, 3 * H_, H_,
             (long)S_ * S_, HD_, HD_, NH_, 1.f, 0);
        // output projection
        gemm(abuf, attn_out_w + (long)l * H_ * H_, attn_out_b + (long)l * H_,
             e0, S_, H_, H_, H_, H_, 1, H_, 0, 0, 0, 1, 1.f, 0);
        ln_kernel<<<S_, H_>>>(cur, e0, ln1_g + l * H_, ln1_b + l * H_);
        // FF
        gemm(cur, ff1_w + (long)l * FF_ * H_, ff1_b + (long)l * FF_,
             ffbuf, S_, FF_, H_, H_, H_, 1, FF_, 0, 0, 0, 1, 1.f, 1);
        gemm(ffbuf, ff2_w + (long)l * H_ * FF_, ff2_b + (long)l * H_,
             e0, S_, H_, FF_, FF_, FF_, 1, H_, 0, 0, 0, 1, 1.f, 0);
        ln_kernel<<<S_, H_>>>(cur, e0, ln2_g + l * H_, ln2_b + l * H_);
    }

    // 4) fc + vocab logits + log_softmax
    gemm(cur, fc_w, fc_b, e0, S_, H_, H_, H_, H_, 1, H_, 0, 0, 0, 1, 1.f, 0);
    gemm(e0, out_w, out_b, out, S_, V_, H_, H_, H_, 1, V_, 0, 0, 0, 1, 1.f, 0);
    logsoftmax_kernel<<<S_, 256>>>(out);
}

// round 3
// speedup vs baseline: 6.8789x; 1.7003x over previous
#include <cuda_runtime.h>
#include <cuda_bf16.h>
#include <math.h>

#define S_   4096
#define E_   128
#define H_   256
#define NE_  4
#define NH_  4
#define HD_  64
#define FF_  2048
#define NL_  2
#define V_   10000
#define EPS_ 1e-5f
#define SCALE_ 0.125f   /* 1/sqrt(64) */

// ---------------- scratch (device globals; allocation-free) ----------------
__device__ float g_h  [S_ * H_];
__device__ float g_y  [S_ * H_];
__device__ float g_e0 [S_ * H_];
__device__ float g_e1 [S_ * H_];
__device__ float g_qkv[S_ * 3 * H_];
__device__ float g_a  [S_ * H_];
__device__ float g_ff [S_ * FF_];
__device__ float g_vals[S_ * 2];
__device__ int   g_sel[2];

// ---------------- embed gather ----------------
__global__ void embed_kernel(const int* __restrict__ x, const float* __restrict__ emb,
                             float* __restrict__ out) {
    int s = blockIdx.x;
    int d = threadIdx.x;           // E_ = 128 threads
    out[s * E_ + d] = emb[(long)x[s] * E_ + d];
}

// ---------------- MoE gate ----------------
__global__ void gate_kernel(const float* __restrict__ x, int din,
                            const float* __restrict__ gw, const float* __restrict__ gb,
                            float* __restrict__ vals, int* __restrict__ sel) {
    int gtid = blockIdx.x * blockDim.x + threadIdx.x;
    int tok  = gtid >> 5;
    int lane = gtid & 31;
    if (tok >= S_) return;
    const float* xr = x + (long)tok * din;
    float p0 = 0.f, p1 = 0.f, p2 = 0.f, p3 = 0.f;
    for (int d = lane; d < din; d += 32) {
        float xv = xr[d];
        p0 += xv * gw[0 * din + d];
        p1 += xv * gw[1 * din + d];
        p2 += xv * gw[2 * din + d];
        p3 += xv * gw[3 * din + d];
    }
    #pragma unroll
    for (int o = 16; o > 0; o >>= 1) {
        p0 += __shfl_xor_sync(0xffffffffu, p0, o);
        p1 += __shfl_xor_sync(0xffffffffu, p1, o);
        p2 += __shfl_xor_sync(0xffffffffu, p2, o);
        p3 += __shfl_xor_sync(0xffffffffu, p3, o);
    }
    if (lane == 0) {
        float sc[4] = { p0 + gb[0], p1 + gb[1], p2 + gb[2], p3 + gb[3] };
        float m = fmaxf(fmaxf(sc[0], sc[1]), fmaxf(sc[2], sc[3]));
        float e[4]; float sum = 0.f;
        #pragma unroll
        for (int i = 0; i < 4; i++) { e[i] = expf(sc[i] - m); sum += e[i]; }
        float inv = 1.f / sum;
        #pragma unroll
        for (int i = 0; i < 4; i++) e[i] *= inv;
        int i0 = 0;
        #pragma unroll
        for (int i = 1; i < 4; i++) if (e[i] > e[i0]) i0 = i;
        int i1 = -1;
        #pragma unroll
        for (int i = 0; i < 4; i++) {
            if (i == i0) continue;
            if (i1 < 0 || e[i] > e[i1]) i1 = i;
        }
        vals[tok * 2 + 0] = e[i0];
        vals[tok * 2 + 1] = e[i1];
        if (tok == 0) { sel[0] = i0; sel[1] = i1; }
    }
}

// ---------------- MoE combine ----------------
__global__ void moe_combine(const float* __restrict__ e0, const float* __restrict__ e1,
                            const float* __restrict__ eb, const float* __restrict__ vals,
                            const int* __restrict__ sel, float* __restrict__ out) {
    long i = (long)blockIdx.x * blockDim.x + threadIdx.x;
    if (i >= (long)S_ * H_) return;
    int s = (int)(i / H_);
    int h = (int)(i % H_);
    float b0 = eb[sel[0] * H_ + h];
    float b1 = eb[sel[1] * H_ + h];
    out[i] = vals[s * 2] * (e0[i] + b0) + vals[s * 2 + 1] * (e1[i] + b1);
}

#define MMA_BF16(ACC, A0, A1, A2, A3, B0, B1)                                  \
    asm volatile(                                                              \
        "mma.sync.aligned.m16n8k16.row.col.f32.bf16.bf16.f32 "                 \
        "{%0,%1,%2,%3}, {%4,%5,%6,%7}, {%8,%9}, {%0,%1,%2,%3};\n"              \
        : "+f"((ACC)[0]), "+f"((ACC)[1]), "+f"((ACC)[2]), "+f"((ACC)[3])       \
        : "r"(A0), "r"(A1), "r"(A2), "r"(A3), "r"(B0), "r"(B1))

static __device__ __forceinline__ unsigned packbf(float x, float y) {
    __nv_bfloat162 p = __float22bfloat162_rn(make_float2(x, y));
    return *(unsigned*)&p;
}

// ---------------- fused flash attention ----------------
// qkv: [S, 3H] fp32 (q | k | v, each [S, NH, HD]). o: [S, H] fp32.
// grid (S/128, NH), 256 threads (8 warps; warp w owns Q rows [w*16, w*16+16)).
__global__ __launch_bounds__(256)
void flash_attn(const float* __restrict__ qkv, float* __restrict__ o) {
    constexpr int BM = 128, BN = 64, D = HD_, PD = 8;
    __shared__ __align__(16) __nv_bfloat16 Qs[BM][D + PD];
    __shared__ __align__(16) __nv_bfloat16 Ks[BN][D + PD];
    __shared__ __align__(16) __nv_bfloat16 Vs[D][BN + PD];

    int h  = blockIdx.y;
    int bm = blockIdx.x * BM;
    int tid = threadIdx.x;
    int lane = tid & 31;
    int w = tid >> 5;
    int g = lane >> 2;   // 0..7
    int q = lane & 3;    // 0..3

    const float* Qp = qkv + h * HD_;            // + row*768
    const float* Kp = qkv + H_ + h * HD_;
    const float* Vp = qkv + 2 * H_ + h * HD_;

    // load Q tile (128 x 64 fp32 -> bf16): 2048 float4, 8 per thread
    #pragma unroll
    for (int i = 0; i < 8; i++) {
        int idx = tid + i * 256;
        int row = idx >> 4;
        int d4  = idx & 15;
        float4 v = *(const float4*)(Qp + (long)(bm + row) * (3 * H_) + d4 * 4);
        *(unsigned*)&Qs[row][d4 * 4]     = packbf(v.x, v.y);
        *(unsigned*)&Qs[row][d4 * 4 + 2] = packbf(v.z, v.w);
    }

    float m0 = -1e30f, m1 = -1e30f, l0 = 0.f, l1 = 0.f;
    float out[8][4];
    #pragma unroll
    for (int ot = 0; ot < 8; ot++)
        #pragma unroll
        for (int r = 0; r < 4; r++) out[ot][r] = 0.f;

    int rowA = w * 16 + g;

    for (int j = 0; j < S_ / BN; j++) {
        __syncthreads();
        // load K tile [64 keys x 64 d]
        #pragma unroll
        for (int i = 0; i < 4; i++) {
            int idx = tid + i * 256;
            int key = idx >> 4;
            int d4  = idx & 15;
            float4 v = *(const float4*)(Kp + (long)(j * BN + key) * (3 * H_) + d4 * 4);
            *(unsigned*)&Ks[key][d4 * 4]     = packbf(v.x, v.y);
            *(unsigned*)&Ks[key][d4 * 4 + 2] = packbf(v.z, v.w);
        }
        // load V tile transposed: Vs[d][key]
        #pragma unroll
        for (int i = 0; i < 4; i++) {
            int idx = tid + i * 256;
            int key = idx >> 4;
            int d4  = idx & 15;
            float4 v = *(const float4*)(Vp + (long)(j * BN + key) * (3 * H_) + d4 * 4);
            Vs[d4 * 4 + 0][key] = __float2bfloat16_rn(v.x);
            Vs[d4 * 4 + 1][key] = __float2bfloat16_rn(v.y);
            Vs[d4 * 4 + 2][key] = __float2bfloat16_rn(v.z);
            Vs[d4 * 4 + 3][key] = __float2bfloat16_rn(v.w);
        }
        __syncthreads();

        // S = Q K^T  (per warp: m16 x n64 x k64)
        float acc[8][4];
        #pragma unroll
        for (int nt = 0; nt < 8; nt++)
            #pragma unroll
            for (int r = 0; r < 4; r++) acc[nt][r] = 0.f;
        #pragma unroll
        for (int kc = 0; kc < 4; kc++) {
            int ac = kc * 16 + q * 2;
            unsigned a0 = *(const unsigned*)&Qs[rowA][ac];
            unsigned a1 = *(const unsigned*)&Qs[rowA + 8][ac];
            unsigned a2 = *(const unsigned*)&Qs[rowA][ac + 8];
            unsigned a3 = *(const unsigned*)&Qs[rowA + 8][ac + 8];
            #pragma unroll
            for (int nt = 0; nt < 8; nt++) {
                unsigned b0 = *(const unsigned*)&Ks[nt * 8 + g][ac];
                unsigned b1 = *(const unsigned*)&Ks[nt * 8 + g][ac + 8];
                MMA_BF16(acc[nt], a0, a1, a2, a3, b0, b1);
            }
        }

        // online softmax (rows g and g+8 of this warp's m16)
        float tm0 = -1e30f, tm1 = -1e30f;
        #pragma unroll
        for (int nt = 0; nt < 8; nt++) {
            acc[nt][0] *= SCALE_; acc[nt][1] *= SCALE_;
            acc[nt][2] *= SCALE_; acc[nt][3] *= SCALE_;
            tm0 = fmaxf(tm0, fmaxf(acc[nt][0], acc[nt][1]));
            tm1 = fmaxf(tm1, fmaxf(acc[nt][2], acc[nt][3]));
        }
        tm0 = fmaxf(tm0, __shfl_xor_sync(0xffffffffu, tm0, 1));
        tm0 = fmaxf(tm0, __shfl_xor_sync(0xffffffffu, tm0, 2));
        tm1 = fmaxf(tm1, __shfl_xor_sync(0xffffffffu, tm1, 1));
        tm1 = fmaxf(tm1, __shfl_xor_sync(0xffffffffu, tm1, 2));
        float mn0 = fmaxf(m0, tm0), mn1 = fmaxf(m1, tm1);
        float corr0 = __expf(m0 - mn0), corr1 = __expf(m1 - mn1);
        float s0 = 0.f, s1 = 0.f;
        #pragma unroll
        for (int nt = 0; nt < 8; nt++) {
            acc[nt][0] = __expf(acc[nt][0] - mn0);
            acc[nt][1] = __expf(acc[nt][1] - mn0);
            acc[nt][2] = __expf(acc[nt][2] - mn1);
            acc[nt][3] = __expf(acc[nt][3] - mn1);
            s0 += acc[nt][0] + acc[nt][1];
            s1 += acc[nt][2] + acc[nt][3];
        }
        m0 = mn0; m1 = mn1;
        l0 = l0 * corr0 + s0;
        l1 = l1 * corr1 + s1;
        #pragma unroll
        for (int ot = 0; ot < 8; ot++) {
            out[ot][0] *= corr0; out[ot][1] *= corr0;
            out[ot][2] *= corr1; out[ot][3] *= corr1;
        }

        // O += P V   (P fragments come straight from acc layout)
        #pragma unroll
        for (int kc = 0; kc < 4; kc++) {
            unsigned a0 = packbf(acc[2 * kc][0],     acc[2 * kc][1]);
            unsigned a1 = packbf(acc[2 * kc][2],     acc[2 * kc][3]);
            unsigned a2 = packbf(acc[2 * kc + 1][0], acc[2 * kc + 1][1]);
            unsigned a3 = packbf(acc[2 * kc + 1][2], acc[2 * kc + 1][3]);
            int kb = kc * 16 + q * 2;
            #pragma unroll
            for (int ot = 0; ot < 8; ot++) {
                unsigned b0 = *(const unsigned*)&Vs[ot * 8 + g][kb];
                unsigned b1 = *(const unsigned*)&Vs[ot * 8 + g][kb + 8];
                MMA_BF16(out[ot], a0, a1, a2, a3, b0, b1);
            }
        }
    }

    // finalize: reduce l over q-lanes, normalize, store fp32
    l0 += __shfl_xor_sync(0xffffffffu, l0, 1);
    l0 += __shfl_xor_sync(0xffffffffu, l0, 2);
    l1 += __shfl_xor_sync(0xffffffffu, l1, 1);
    l1 += __shfl_xor_sync(0xffffffffu, l1, 2);
    float inv0 = 1.f / l0, inv1 = 1.f / l1;
    int row0 = bm + w * 16 + g;
    #pragma unroll
    for (int ot = 0; ot < 8; ot++) {
        int col = h * HD_ + ot * 8 + q * 2;
        *(float2*)(o + (long)row0 * H_ + col) =
            make_float2(out[ot][0] * inv0, out[ot][1] * inv0);
        *(float2*)(o + (long)(row0 + 8) * H_ + col) =
            make_float2(out[ot][2] * inv1, out[ot][3] * inv1);
    }
}

// ---------------- tensor-core GEMM (bf16 mma.sync, fp32 accum) ----------------
__global__ __launch_bounds__(256)
void gemm_tc(const float* __restrict__ A, const float* __restrict__ B,
             const float* __restrict__ bias, float* __restrict__ C,
             int M, int N, int K,
             int as_m, int bs_n, int bs_k, int ldc,
             long batchA, long batchB, long batchC,
             float alpha, int do_relu,
             const int* __restrict__ sel, int selk, long selStride) {
    constexpr int BM = 128, BN = 64, BK = 32;
    constexpr int PAD = 8;
    __shared__ __align__(16) __nv_bfloat16 As[BM][BK + PAD];
    __shared__ __align__(16) __nv_bfloat16 Bs[BN][BK + PAD];

    A += (long)blockIdx.z * batchA;
    B += (long)blockIdx.z * batchB;
    C += (long)blockIdx.z * batchC;
    if (sel) B += (long)sel[selk] * selStride;

    int bm = blockIdx.y * BM;
    int bn = blockIdx.x * BN;
    int tid  = threadIdx.x;
    int lane = tid & 31;
    int wid  = tid >> 5;
    int warpM = (wid & 3) * 32;
    int warpN = (wid >> 2) * 32;

    float acc[2][4][4];
    #pragma unroll
    for (int mt = 0; mt < 2; mt++)
        #pragma unroll
        for (int nt = 0; nt < 4; nt++)
            #pragma unroll
            for (int r = 0; r < 4; r++) acc[mt][nt][r] = 0.f;

    int g = lane >> 2;
    int q = lane & 3;

    for (int k0 = 0; k0 < K; k0 += BK) {
        #pragma unroll
        for (int t = 0; t < 4; t++) {
            int idx = tid + t * 256;
            int row = idx >> 3;
            int kq  = idx & 7;
            const float4 v = *(const float4*)(A + (long)(bm + row) * as_m + k0 + kq * 4);
            *(unsigned*)&As[row][kq * 4]     = packbf(v.x, v.y);
            *(unsigned*)&As[row][kq * 4 + 2] = packbf(v.z, v.w);
        }
        if (bs_k == 1) {
            #pragma unroll
            for (int t = 0; t < 2; t++) {
                int idx = tid + t * 256;
                int row = idx >> 3;
                int kq  = idx & 7;
                int gn  = bn + row;
                float4 v = make_float4(0.f, 0.f, 0.f, 0.f);
                if (gn < N) v = *(const float4*)(B + (long)gn * bs_n + k0 + kq * 4);
                *(unsigned*)&Bs[row][kq * 4]     = packbf(v.x, v.y);
                *(unsigned*)&Bs[row][kq * 4 + 2] = packbf(v.z, v.w);
            }
        } else {
            #pragma unroll
            for (int t = 0; t < 8; t++) {
                int idx = tid + t * 256;
                int n = idx & 63;
                int k = idx >> 6;
                int gn = bn + n;
                float v = (gn < N) ? B[(long)gn * bs_n + (long)(k0 + k) * bs_k] : 0.f;
                Bs[n][k] = __float2bfloat16_rn(v);
            }
        }
        __syncthreads();

        #pragma unroll
        for (int ks = 0; ks < BK; ks += 16) {
            unsigned a[2][4], b[4][2];
            int ac = ks + q * 2;
            #pragma unroll
            for (int mt = 0; mt < 2; mt++) {
                int r = warpM + mt * 16 + g;
                a[mt][0] = *(const unsigned*)&As[r][ac];
                a[mt][1] = *(const unsigned*)&As[r + 8][ac];
                a[mt][2] = *(const unsigned*)&As[r][ac + 8];
                a[mt][3] = *(const unsigned*)&As[r + 8][ac + 8];
            }
            #pragma unroll
            for (int nt = 0; nt < 4; nt++) {
                int nr = warpN + nt * 8 + g;
                b[nt][0] = *(const unsigned*)&Bs[nr][ac];
                b[nt][1] = *(const unsigned*)&Bs[nr][ac + 8];
            }
            #pragma unroll
            for (int mt = 0; mt < 2; mt++)
                #pragma unroll
                for (int nt = 0; nt < 4; nt++)
                    MMA_BF16(acc[mt][nt], a[mt][0], a[mt][1], a[mt][2], a[mt][3],
                             b[nt][0], b[nt][1]);
        }
        __syncthreads();
    }

    #pragma unroll
    for (int mt = 0; mt < 2; mt++) {
        int row0 = bm + warpM + mt * 16 + g;
        #pragma unroll
        for (int nt = 0; nt < 4; nt++) {
            int col = bn + warpN + nt * 8 + q * 2;
            if (col >= N) continue;
            float b0 = bias ? bias[col]     : 0.f;
            float b1 = bias ? bias[col + 1] : 0.f;
            float v00 = acc[mt][nt][0] * alpha + b0;
            float v01 = acc[mt][nt][1] * alpha + b1;
            float v10 = acc[mt][nt][2] * alpha + b0;
            float v11 = acc[mt][nt][3] * alpha + b1;
            if (do_relu) {
                v00 = fmaxf(v00, 0.f); v01 = fmaxf(v01, 0.f);
                v10 = fmaxf(v10, 0.f); v11 = fmaxf(v11, 0.f);
            }
            *(float2*)(C + (long)row0 * ldc + col)       = make_float2(v00, v01);
            *(float2*)(C + (long)(row0 + 8) * ldc + col) = make_float2(v10, v11);
        }
    }
}

// ---------------- residual add + LayerNorm (in place on h) ----------------
__global__ void ln_kernel(float* __restrict__ h, const float* __restrict__ t,
                          const float* __restrict__ g, const float* __restrict__ b) {
    __shared__ float red[H_];
    int s = blockIdx.x;
    int d = threadIdx.x;
    float v = h[s * H_ + d] + t[s * H_ + d];
    red[d] = v;
    __syncthreads();
    for (int o = H_ / 2; o > 0; o >>= 1) {
        if (d < o) red[d] += red[d + o];
        __syncthreads();
    }
    float m = red[0] * (1.f / H_);
    __syncthreads();
    float c = v - m;
    red[d] = c * c;
    __syncthreads();
    for (int o = H_ / 2; o > 0; o >>= 1) {
        if (d < o) red[d] += red[d + o];
        __syncthreads();
    }
    float var = red[0] * (1.f / H_);
    h[s * H_ + d] = c * rsqrtf(var + EPS_) * g[d] + b[d];
}

// ---------------- final log_softmax over vocab rows (len 10000), in place ----------------
__global__ void logsoftmax_kernel(float* __restrict__ out) {
    __shared__ float red[256];
    float* p = out + (long)blockIdx.x * V_;
    int t = threadIdx.x;
    float loc[40];
    float m = -1e30f;
    #pragma unroll
    for (int i = 0; i < 40; i++) {
        int c = t + i * 256;
        loc[i] = (c < V_) ? p[c] : -1e30f;
        m = fmaxf(m, loc[i]);
    }
    red[t] = m;
    __syncthreads();
    for (int o = 128; o > 0; o >>= 1) {
        if (t < o) red[t] = fmaxf(red[t], red[t + o]);
        __syncthreads();
    }
    m = red[0];
    __syncthreads();
    float sum = 0.f;
    #pragma unroll
    for (int i = 0; i < 40; i++) {
        int c = t + i * 256;
        if (c < V_) sum += expf(loc[i] - m);
    }
    red[t] = sum;
    __syncthreads();
    for (int o = 128; o > 0; o >>= 1) {
        if (t < o) red[t] += red[t + o];
        __syncthreads();
    }
    float lse = m + logf(red[0]);
    #pragma unroll
    for (int i = 0; i < 40; i++) {
        int c = t + i * 256;
        if (c < V_) p[c] = loc[i] - lse;
    }
}

// ---------------- host side ----------------
static inline void gemm(const float* A, const float* B, const float* bias, float* C,
                        int M, int N, int K,
                        int as_m, int bs_n, int bs_k, int ldc,
                        long bA, long bB, long bC, int Z,
                        float alpha, int relu,
                        const int* sel = nullptr, int selk = 0, long selStride = 0) {
    dim3 grid((N + 63) / 64, M / 128, Z);
    gemm_tc<<<grid, 256>>>(A, B, bias, C, M, N, K,
                           as_m, bs_n, bs_k, ldc,
                           bA, bB, bC, alpha, relu,
                           sel, selk, selStride);
}

extern "C" void kernel_launch(void* const* d_in, const int* in_sizes, int n_in,
                              void* d_out, int out_size) {
    const int*   x         = (const int*)d_in[0];
    const float* emb       = (const float*)d_in[1];
    const float* moe_gw[3] = { (const float*)d_in[2], (const float*)d_in[6], (const float*)d_in[10] };
    const float* moe_gb[3] = { (const float*)d_in[3], (const float*)d_in[7], (const float*)d_in[11] };
    const float* moe_ew[3] = { (const float*)d_in[4], (const float*)d_in[8], (const float*)d_in[12] };
    const float* moe_eb[3] = { (const float*)d_in[5], (const float*)d_in[9], (const float*)d_in[13] };
    const float* attn_in_w  = (const float*)d_in[14];
    const float* attn_in_b  = (const float*)d_in[15];
    const float* attn_out_w = (const float*)d_in[16];
    const float* attn_out_b = (const float*)d_in[17];
    const float* ln1_g = (const float*)d_in[18];
    const float* ln1_b = (const float*)d_in[19];
    const float* ln2_g = (const float*)d_in[20];
    const float* ln2_b = (const float*)d_in[21];
    const float* ff1_w = (const float*)d_in[22];
    const float* ff1_b = (const float*)d_in[23];
    const float* ff2_w = (const float*)d_in[24];
    const float* ff2_b = (const float*)d_in[25];
    const float* fc_w  = (const float*)d_in[26];
    const float* fc_b  = (const float*)d_in[27];
    const float* out_w = (const float*)d_in[28];
    const float* out_b = (const float*)d_in[29];
    float* out = (float*)d_out;

    float *hbuf, *ybuf, *e0, *e1, *qkv, *abuf, *ffbuf, *vals;
    int* sel;
    cudaGetSymbolAddress((void**)&hbuf,  g_h);
    cudaGetSymbolAddress((void**)&ybuf,  g_y);
    cudaGetSymbolAddress((void**)&e0,    g_e0);
    cudaGetSymbolAddress((void**)&e1,    g_e1);
    cudaGetSymbolAddress((void**)&qkv,   g_qkv);
    cudaGetSymbolAddress((void**)&abuf,  g_a);
    cudaGetSymbolAddress((void**)&ffbuf, g_ff);
    cudaGetSymbolAddress((void**)&vals,  g_vals);
    cudaGetSymbolAddress((void**)&sel,   g_sel);

    // 1) embedding gather -> hbuf [S, E]
    embed_kernel<<<S_, E_>>>(x, emb, hbuf);

    // 2) three MoE blocks; ping-pong hbuf/ybuf
    const float* moe_in[3] = { hbuf, ybuf, hbuf };
    float*       moe_out_p[3] = { ybuf, hbuf, ybuf };
    int          moe_din[3] = { E_, H_, H_ };
    for (int i = 0; i < 3; i++) {
        int din = moe_din[i];
        gate_kernel<<<(S_ * 32) / 256, 256>>>(moe_in[i], din, moe_gw[i], moe_gb[i], vals, sel);
        gemm(moe_in[i], moe_ew[i], nullptr, e0, S_, H_, din, din, din, 1, H_,
             0, 0, 0, 1, 1.f, 0, sel, 0, (long)H_ * din);
        gemm(moe_in[i], moe_ew[i], nullptr, e1, S_, H_, din, din, din, 1, H_,
             0, 0, 0, 1, 1.f, 0, sel, 1, (long)H_ * din);
        moe_combine<<<(S_ * H_) / 256, 256>>>(e0, e1, moe_eb[i], vals, sel, moe_out_p[i]);
    }
    float* cur = ybuf;   // after moe2

    // 3) transformer layers
    for (int l = 0; l < NL_; l++) {
        gemm(cur, attn_in_w + (long)l * 3 * H_ * H_, attn_in_b + (long)l * 3 * H_,
             qkv, S_, 3 * H_, H_, H_, H_, 1, 3 * H_, 0, 0, 0, 1, 1.f, 0);
        flash_attn<<<dim3(S_ / 128, NH_), 256>>>(qkv, abuf);
        gemm(abuf, attn_out_w + (long)l * H_ * H_, attn_out_b + (long)l * H_,
             e0, S_, H_, H_, H_, H_, 1, H_, 0, 0, 0, 1, 1.f, 0);
        ln_kernel<<<S_, H_>>>(cur, e0, ln1_g + l * H_, ln1_b + l * H_);
        gemm(cur, ff1_w + (long)l * FF_ * H_, ff1_b + (long)l * FF_,
             ffbuf, S_, FF_, H_, H_, H_, 1, FF_, 0, 0, 0, 1, 1.f, 1);
        gemm(ffbuf, ff2_w + (long)l * H_ * FF_, ff2_b + (long)l * H_,
             e0, S_, H_, FF_, FF_, FF_, 1, H_, 0, 0, 0, 1, 1.f, 0);
        ln_kernel<<<S_, H_>>>(cur, e0, ln2_g + l * H_, ln2_b + l * H_);
    }

    // 4) fc + vocab logits + log_softmax
    gemm(cur, fc_w, fc_b, e0, S_, H_, H_, H_, H_, 1, H_, 0, 0, 0, 1, 1.f, 0);
    gemm(e0, out_w, out_b, out, S_, V_, H_, H_, H_, 1, V_, 0, 0, 0, 1, 1.f, 0);
    logsoftmax_kernel<<<S_, 256>>>(out);
}

// round 4
// speedup vs baseline: 8.1375x; 1.1830x over previous
#include <cuda_runtime.h>
#include <cuda_bf16.h>
#include <math.h>

#define S_   4096
#define E_   128
#define H_   256
#define NE_  4
#define NH_  4
#define HD_  64
#define FF_  2048
#define NL_  2
#define V_   10000
#define EPS_ 1e-5f
#define SCALE_ 0.125f   /* 1/sqrt(64) */

// ---------------- scratch (device globals; allocation-free) ----------------
__device__ float g_h  [S_ * H_];
__device__ float g_y  [S_ * H_];
__device__ float g_e0 [2 * S_ * H_];   // both experts, z-batched
__device__ float g_qkv[S_ * 3 * H_];
__device__ float g_a  [S_ * H_];
__device__ float g_ff [S_ * FF_];
__device__ float g_vals[S_ * 2];
__device__ int   g_sel[2];

// ---------------- embed gather ----------------
__global__ void embed_kernel(const int* __restrict__ x, const float* __restrict__ emb,
                             float* __restrict__ out) {
    int s = blockIdx.x;
    int d = threadIdx.x;           // E_ = 128 threads
    out[s * E_ + d] = emb[(long)x[s] * E_ + d];
}

// ---------------- MoE gate ----------------
__global__ void gate_kernel(const float* __restrict__ x, int din,
                            const float* __restrict__ gw, const float* __restrict__ gb,
                            float* __restrict__ vals, int* __restrict__ sel) {
    int gtid = blockIdx.x * blockDim.x + threadIdx.x;
    int tok  = gtid >> 5;
    int lane = gtid & 31;
    if (tok >= S_) return;
    const float* xr = x + (long)tok * din;
    float p0 = 0.f, p1 = 0.f, p2 = 0.f, p3 = 0.f;
    for (int d = lane; d < din; d += 32) {
        float xv = xr[d];
        p0 += xv * gw[0 * din + d];
        p1 += xv * gw[1 * din + d];
        p2 += xv * gw[2 * din + d];
        p3 += xv * gw[3 * din + d];
    }
    #pragma unroll
    for (int o = 16; o > 0; o >>= 1) {
        p0 += __shfl_xor_sync(0xffffffffu, p0, o);
        p1 += __shfl_xor_sync(0xffffffffu, p1, o);
        p2 += __shfl_xor_sync(0xffffffffu, p2, o);
        p3 += __shfl_xor_sync(0xffffffffu, p3, o);
    }
    if (lane == 0) {
        float sc[4] = { p0 + gb[0], p1 + gb[1], p2 + gb[2], p3 + gb[3] };
        float m = fmaxf(fmaxf(sc[0], sc[1]), fmaxf(sc[2], sc[3]));
        float e[4]; float sum = 0.f;
        #pragma unroll
        for (int i = 0; i < 4; i++) { e[i] = expf(sc[i] - m); sum += e[i]; }
        float inv = 1.f / sum;
        #pragma unroll
        for (int i = 0; i < 4; i++) e[i] *= inv;
        int i0 = 0;
        #pragma unroll
        for (int i = 1; i < 4; i++) if (e[i] > e[i0]) i0 = i;
        int i1 = -1;
        #pragma unroll
        for (int i = 0; i < 4; i++) {
            if (i == i0) continue;
            if (i1 < 0 || e[i] > e[i1]) i1 = i;
        }
        vals[tok * 2 + 0] = e[i0];
        vals[tok * 2 + 1] = e[i1];
        if (tok == 0) { sel[0] = i0; sel[1] = i1; }
    }
}

// ---------------- MoE combine ----------------
__global__ void moe_combine(const float* __restrict__ e0, const float* __restrict__ e1,
                            const float* __restrict__ eb, const float* __restrict__ vals,
                            const int* __restrict__ sel, float* __restrict__ out) {
    long i = (long)blockIdx.x * blockDim.x + threadIdx.x;
    if (i >= (long)S_ * H_) return;
    int s = (int)(i / H_);
    int h = (int)(i % H_);
    float b0 = eb[sel[0] * H_ + h];
    float b1 = eb[sel[1] * H_ + h];
    out[i] = vals[s * 2] * (e0[i] + b0) + vals[s * 2 + 1] * (e1[i] + b1);
}

#define MMA_BF16(ACC, A0, A1, A2, A3, B0, B1)                                  \
    asm volatile(                                                              \
        "mma.sync.aligned.m16n8k16.row.col.f32.bf16.bf16.f32 "                 \
        "{%0,%1,%2,%3}, {%4,%5,%6,%7}, {%8,%9}, {%0,%1,%2,%3};\n"              \
        : "+f"((ACC)[0]), "+f"((ACC)[1]), "+f"((ACC)[2]), "+f"((ACC)[3])       \
        : "r"(A0), "r"(A1), "r"(A2), "r"(A3), "r"(B0), "r"(B1))

static __device__ __forceinline__ unsigned packbf(float x, float y) {
    __nv_bfloat162 p = __float22bfloat162_rn(make_float2(x, y));
    return *(unsigned*)&p;
}

// ---------------- fused flash attention ----------------
// qkv: [S, 3H] fp32 (q | k | v, each [S, NH, HD]). o: [S, H] fp32.
// grid (S/128, NH), 256 threads (8 warps; warp w owns Q rows [w*16, w*16+16)).
__global__ __launch_bounds__(256)
void flash_attn(const float* __restrict__ qkv, float* __restrict__ o) {
    constexpr int BM = 128, BN = 64, D = HD_, PD = 8;
    __shared__ __align__(16) __nv_bfloat16 Qs[BM][D + PD];
    __shared__ __align__(16) __nv_bfloat16 Ks[BN][D + PD];
    __shared__ __align__(16) __nv_bfloat16 Vs[D][BN + PD];

    int h  = blockIdx.y;
    int bm = blockIdx.x * BM;
    int tid = threadIdx.x;
    int lane = tid & 31;
    int w = tid >> 5;
    int g = lane >> 2;   // 0..7
    int q = lane & 3;    // 0..3

    const float* Qp = qkv + h * HD_;            // + row*768
    const float* Kp = qkv + H_ + h * HD_;
    const float* Vp = qkv + 2 * H_ + h * HD_;

    #pragma unroll
    for (int i = 0; i < 8; i++) {
        int idx = tid + i * 256;
        int row = idx >> 4;
        int d4  = idx & 15;
        float4 v = *(const float4*)(Qp + (long)(bm + row) * (3 * H_) + d4 * 4);
        *(unsigned*)&Qs[row][d4 * 4]     = packbf(v.x, v.y);
        *(unsigned*)&Qs[row][d4 * 4 + 2] = packbf(v.z, v.w);
    }

    float m0 = -1e30f, m1 = -1e30f, l0 = 0.f, l1 = 0.f;
    float out[8][4];
    #pragma unroll
    for (int ot = 0; ot < 8; ot++)
        #pragma unroll
        for (int r = 0; r < 4; r++) out[ot][r] = 0.f;

    int rowA = w * 16 + g;

    for (int j = 0; j < S_ / BN; j++) {
        __syncthreads();
        #pragma unroll
        for (int i = 0; i < 4; i++) {
            int idx = tid + i * 256;
            int key = idx >> 4;
            int d4  = idx & 15;
            float4 v = *(const float4*)(Kp + (long)(j * BN + key) * (3 * H_) + d4 * 4);
            *(unsigned*)&Ks[key][d4 * 4]     = packbf(v.x, v.y);
            *(unsigned*)&Ks[key][d4 * 4 + 2] = packbf(v.z, v.w);
        }
        #pragma unroll
        for (int i = 0; i < 4; i++) {
            int idx = tid + i * 256;
            int key = idx >> 4;
            int d4  = idx & 15;
            float4 v = *(const float4*)(Vp + (long)(j * BN + key) * (3 * H_) + d4 * 4);
            Vs[d4 * 4 + 0][key] = __float2bfloat16_rn(v.x);
            Vs[d4 * 4 + 1][key] = __float2bfloat16_rn(v.y);
            Vs[d4 * 4 + 2][key] = __float2bfloat16_rn(v.z);
            Vs[d4 * 4 + 3][key] = __float2bfloat16_rn(v.w);
        }
        __syncthreads();

        float acc[8][4];
        #pragma unroll
        for (int nt = 0; nt < 8; nt++)
            #pragma unroll
            for (int r = 0; r < 4; r++) acc[nt][r] = 0.f;
        #pragma unroll
        for (int kc = 0; kc < 4; kc++) {
            int ac = kc * 16 + q * 2;
            unsigned a0 = *(const unsigned*)&Qs[rowA][ac];
            unsigned a1 = *(const unsigned*)&Qs[rowA + 8][ac];
            unsigned a2 = *(const unsigned*)&Qs[rowA][ac + 8];
            unsigned a3 = *(const unsigned*)&Qs[rowA + 8][ac + 8];
            #pragma unroll
            for (int nt = 0; nt < 8; nt++) {
                unsigned b0 = *(const unsigned*)&Ks[nt * 8 + g][ac];
                unsigned b1 = *(const unsigned*)&Ks[nt * 8 + g][ac + 8];
                MMA_BF16(acc[nt], a0, a1, a2, a3, b0, b1);
            }
        }

        float tm0 = -1e30f, tm1 = -1e30f;
        #pragma unroll
        for (int nt = 0; nt < 8; nt++) {
            acc[nt][0] *= SCALE_; acc[nt][1] *= SCALE_;
            acc[nt][2] *= SCALE_; acc[nt][3] *= SCALE_;
            tm0 = fmaxf(tm0, fmaxf(acc[nt][0], acc[nt][1]));
            tm1 = fmaxf(tm1, fmaxf(acc[nt][2], acc[nt][3]));
        }
        tm0 = fmaxf(tm0, __shfl_xor_sync(0xffffffffu, tm0, 1));
        tm0 = fmaxf(tm0, __shfl_xor_sync(0xffffffffu, tm0, 2));
        tm1 = fmaxf(tm1, __shfl_xor_sync(0xffffffffu, tm1, 1));
        tm1 = fmaxf(tm1, __shfl_xor_sync(0xffffffffu, tm1, 2));
        float mn0 = fmaxf(m0, tm0), mn1 = fmaxf(m1, tm1);
        float corr0 = __expf(m0 - mn0), corr1 = __expf(m1 - mn1);
        float s0 = 0.f, s1 = 0.f;
        #pragma unroll
        for (int nt = 0; nt < 8; nt++) {
            acc[nt][0] = __expf(acc[nt][0] - mn0);
            acc[nt][1] = __expf(acc[nt][1] - mn0);
            acc[nt][2] = __expf(acc[nt][2] - mn1);
            acc[nt][3] = __expf(acc[nt][3] - mn1);
            s0 += acc[nt][0] + acc[nt][1];
            s1 += acc[nt][2] + acc[nt][3];
        }
        m0 = mn0; m1 = mn1;
        l0 = l0 * corr0 + s0;
        l1 = l1 * corr1 + s1;
        #pragma unroll
        for (int ot = 0; ot < 8; ot++) {
            out[ot][0] *= corr0; out[ot][1] *= corr0;
            out[ot][2] *= corr1; out[ot][3] *= corr1;
        }

        #pragma unroll
        for (int kc = 0; kc < 4; kc++) {
            unsigned a0 = packbf(acc[2 * kc][0],     acc[2 * kc][1]);
            unsigned a1 = packbf(acc[2 * kc][2],     acc[2 * kc][3]);
            unsigned a2 = packbf(acc[2 * kc + 1][0], acc[2 * kc + 1][1]);
            unsigned a3 = packbf(acc[2 * kc + 1][2], acc[2 * kc + 1][3]);
            int kb = kc * 16 + q * 2;
            #pragma unroll
            for (int ot = 0; ot < 8; ot++) {
                unsigned b0 = *(const unsigned*)&Vs[ot * 8 + g][kb];
                unsigned b1 = *(const unsigned*)&Vs[ot * 8 + g][kb + 8];
                MMA_BF16(out[ot], a0, a1, a2, a3, b0, b1);
            }
        }
    }

    l0 += __shfl_xor_sync(0xffffffffu, l0, 1);
    l0 += __shfl_xor_sync(0xffffffffu, l0, 2);
    l1 += __shfl_xor_sync(0xffffffffu, l1, 1);
    l1 += __shfl_xor_sync(0xffffffffu, l1, 2);
    float inv0 = 1.f / l0, inv1 = 1.f / l1;
    int row0 = bm + w * 16 + g;
    #pragma unroll
    for (int ot = 0; ot < 8; ot++) {
        int col = h * HD_ + ot * 8 + q * 2;
        *(float2*)(o + (long)row0 * H_ + col) =
            make_float2(out[ot][0] * inv0, out[ot][1] * inv0);
        *(float2*)(o + (long)(row0 + 8) * H_ + col) =
            make_float2(out[ot][2] * inv1, out[ot][3] * inv1);
    }
}

// ---------------- tensor-core GEMM, register-staged double buffer ----------------
// C[M,N] = A * B^T + bias (+relu). A: [M,K] k-contig (lda=as_m). B row n: k-contig (ldb=bs_n).
// Expert batching: if sel != nullptr, B += sel[blockIdx.z] * selStride, C += z*batchC.
__global__ __launch_bounds__(256, 2)
void gemm_tc(const float* __restrict__ A, const float* __restrict__ B,
             const float* __restrict__ bias, float* __restrict__ C,
             int M, int N, int K,
             int as_m, int bs_n, int ldc,
             long batchC, int do_relu,
             const int* __restrict__ sel, long selStride) {
    constexpr int BM = 128, BN = 64, BK = 32;
    constexpr int PAD = 8;
    __shared__ __align__(16) __nv_bfloat16 As[BM][BK + PAD];
    __shared__ __align__(16) __nv_bfloat16 Bs[BN][BK + PAD];

    if (sel) {
        B += (long)sel[blockIdx.z] * selStride;
        C += (long)blockIdx.z * batchC;
    }

    int bm = blockIdx.y * BM;
    int bn = blockIdx.x * BN;
    int tid  = threadIdx.x;
    int lane = tid & 31;
    int wid  = tid >> 5;
    int warpM = (wid & 3) * 32;
    int warpN = (wid >> 2) * 32;

    float acc[2][4][4];
    #pragma unroll
    for (int mt = 0; mt < 2; mt++)
        #pragma unroll
        for (int nt = 0; nt < 4; nt++)
            #pragma unroll
            for (int r = 0; r < 4; r++) acc[mt][nt][r] = 0.f;

    int g = lane >> 2;
    int q = lane & 3;

    // register staging buffers
    float4 ra[4];
    float4 rb[2];
    int arow[4], akq[4], brow[2], bkq[2];
    #pragma unroll
    for (int t = 0; t < 4; t++) {
        int idx = tid + t * 256;
        arow[t] = idx >> 3;
        akq[t]  = idx & 7;
    }
    #pragma unroll
    for (int t = 0; t < 2; t++) {
        int idx = tid + t * 256;
        brow[t] = idx >> 3;
        bkq[t]  = idx & 7;
    }

    // prologue: load k0 = 0
    #pragma unroll
    for (int t = 0; t < 4; t++)
        ra[t] = *(const float4*)(A + (long)(bm + arow[t]) * as_m + akq[t] * 4);
    #pragma unroll
    for (int t = 0; t < 2; t++) {
        int gn = bn + brow[t];
        rb[t] = (gn < N) ? *(const float4*)(B + (long)gn * bs_n + bkq[t] * 4)
                         : make_float4(0.f, 0.f, 0.f, 0.f);
    }

    for (int k0 = 0; k0 < K; k0 += BK) {
        __syncthreads();   // previous compute done reading smem
        #pragma unroll
        for (int t = 0; t < 4; t++) {
            *(unsigned*)&As[arow[t]][akq[t] * 4]     = packbf(ra[t].x, ra[t].y);
            *(unsigned*)&As[arow[t]][akq[t] * 4 + 2] = packbf(ra[t].z, ra[t].w);
        }
        #pragma unroll
        for (int t = 0; t < 2; t++) {
            *(unsigned*)&Bs[brow[t]][bkq[t] * 4]     = packbf(rb[t].x, rb[t].y);
            *(unsigned*)&Bs[brow[t]][bkq[t] * 4 + 2] = packbf(rb[t].z, rb[t].w);
        }
        __syncthreads();

        // prefetch next tile while computing
        int kn = k0 + BK;
        if (kn < K) {
            #pragma unroll
            for (int t = 0; t < 4; t++)
                ra[t] = *(const float4*)(A + (long)(bm + arow[t]) * as_m + kn + akq[t] * 4);
            #pragma unroll
            for (int t = 0; t < 2; t++) {
                int gn = bn + brow[t];
                rb[t] = (gn < N) ? *(const float4*)(B + (long)gn * bs_n + kn + bkq[t] * 4)
                                 : make_float4(0.f, 0.f, 0.f, 0.f);
            }
        }

        #pragma unroll
        for (int ks = 0; ks < BK; ks += 16) {
            unsigned a[2][4], b[4][2];
            int ac = ks + q * 2;
            #pragma unroll
            for (int mt = 0; mt < 2; mt++) {
                int r = warpM + mt * 16 + g;
                a[mt][0] = *(const unsigned*)&As[r][ac];
                a[mt][1] = *(const unsigned*)&As[r + 8][ac];
                a[mt][2] = *(const unsigned*)&As[r][ac + 8];
                a[mt][3] = *(const unsigned*)&As[r + 8][ac + 8];
            }
            #pragma unroll
            for (int nt = 0; nt < 4; nt++) {
                int nr = warpN + nt * 8 + g;
                b[nt][0] = *(const unsigned*)&Bs[nr][ac];
                b[nt][1] = *(const unsigned*)&Bs[nr][ac + 8];
            }
            #pragma unroll
            for (int mt = 0; mt < 2; mt++)
                #pragma unroll
                for (int nt = 0; nt < 4; nt++)
                    MMA_BF16(acc[mt][nt], a[mt][0], a[mt][1], a[mt][2], a[mt][3],
                             b[nt][0], b[nt][1]);
        }
    }

    #pragma unroll
    for (int mt = 0; mt < 2; mt++) {
        int row0 = bm + warpM + mt * 16 + g;
        #pragma unroll
        for (int nt = 0; nt < 4; nt++) {
            int col = bn + warpN + nt * 8 + q * 2;
            if (col >= N) continue;
            float b0 = bias ? bias[col]     : 0.f;
            float b1 = bias ? bias[col + 1] : 0.f;
            float v00 = acc[mt][nt][0] + b0;
            float v01 = acc[mt][nt][1] + b1;
            float v10 = acc[mt][nt][2] + b0;
            float v11 = acc[mt][nt][3] + b1;
            if (do_relu) {
                v00 = fmaxf(v00, 0.f); v01 = fmaxf(v01, 0.f);
                v10 = fmaxf(v10, 0.f); v11 = fmaxf(v11, 0.f);
            }
            *(float2*)(C + (long)row0 * ldc + col)       = make_float2(v00, v01);
            *(float2*)(C + (long)(row0 + 8) * ldc + col) = make_float2(v10, v11);
        }
    }
}

// ---------------- residual add + LayerNorm (in place on h) ----------------
__global__ void ln_kernel(float* __restrict__ h, const float* __restrict__ t,
                          const float* __restrict__ g, const float* __restrict__ b) {
    __shared__ float red[H_];
    int s = blockIdx.x;
    int d = threadIdx.x;
    float v = h[s * H_ + d] + t[s * H_ + d];
    red[d] = v;
    __syncthreads();
    for (int o = H_ / 2; o > 0; o >>= 1) {
        if (d < o) red[d] += red[d + o];
        __syncthreads();
    }
    float m = red[0] * (1.f / H_);
    __syncthreads();
    float c = v - m;
    red[d] = c * c;
    __syncthreads();
    for (int o = H_ / 2; o > 0; o >>= 1) {
        if (d < o) red[d] += red[d + o];
        __syncthreads();
    }
    float var = red[0] * (1.f / H_);
    h[s * H_ + d] = c * rsqrtf(var + EPS_) * g[d] + b[d];
}

// ---------------- final log_softmax over vocab rows (len 10000), in place ----------------
__global__ void logsoftmax_kernel(float* __restrict__ out) {
    __shared__ float red[256];
    float* p = out + (long)blockIdx.x * V_;
    int t = threadIdx.x;
    float loc[40];
    float m = -1e30f;
    #pragma unroll
    for (int i = 0; i < 40; i++) {
        int c = t + i * 256;
        loc[i] = (c < V_) ? p[c] : -1e30f;
        m = fmaxf(m, loc[i]);
    }
    red[t] = m;
    __syncthreads();
    for (int o = 128; o > 0; o >>= 1) {
        if (t < o) red[t] = fmaxf(red[t], red[t + o]);
        __syncthreads();
    }
    m = red[0];
    __syncthreads();
    float sum = 0.f;
    #pragma unroll
    for (int i = 0; i < 40; i++) {
        int c = t + i * 256;
        if (c < V_) sum += expf(loc[i] - m);
    }
    red[t] = sum;
    __syncthreads();
    for (int o = 128; o > 0; o >>= 1) {
        if (t < o) red[t] += red[t + o];
        __syncthreads();
    }
    float lse = m + logf(red[0]);
    #pragma unroll
    for (int i = 0; i < 40; i++) {
        int c = t + i * 256;
        if (c < V_) p[c] = loc[i] - lse;
    }
}

// ---------------- host side ----------------
static inline void gemm(const float* A, const float* B, const float* bias, float* C,
                        int M, int N, int K,
                        int as_m, int bs_n, int ldc,
                        int relu,
                        int Z = 1, long batchC = 0,
                        const int* sel = nullptr, long selStride = 0) {
    dim3 grid((N + 63) / 64, M / 128, Z);
    gemm_tc<<<grid, 256>>>(A, B, bias, C, M, N, K,
                           as_m, bs_n, ldc, batchC, relu, sel, selStride);
}

extern "C" void kernel_launch(void* const* d_in, const int* in_sizes, int n_in,
                              void* d_out, int out_size) {
    const int*   x         = (const int*)d_in[0];
    const float* emb       = (const float*)d_in[1];
    const float* moe_gw[3] = { (const float*)d_in[2], (const float*)d_in[6], (const float*)d_in[10] };
    const float* moe_gb[3] = { (const float*)d_in[3], (const float*)d_in[7], (const float*)d_in[11] };
    const float* moe_ew[3] = { (const float*)d_in[4], (const float*)d_in[8], (const float*)d_in[12] };
    const float* moe_eb[3] = { (const float*)d_in[5], (const float*)d_in[9], (const float*)d_in[13] };
    const float* attn_in_w  = (const float*)d_in[14];
    const float* attn_in_b  = (const float*)d_in[15];
    const float* attn_out_w = (const float*)d_in[16];
    const float* attn_out_b = (const float*)d_in[17];
    const float* ln1_g = (const float*)d_in[18];
    const float* ln1_b = (const float*)d_in[19];
    const float* ln2_g = (const float*)d_in[20];
    const float* ln2_b = (const float*)d_in[21];
    const float* ff1_w = (const float*)d_in[22];
    const float* ff1_b = (const float*)d_in[23];
    const float* ff2_w = (const float*)d_in[24];
    const float* ff2_b = (const float*)d_in[25];
    const float* fc_w  = (const float*)d_in[26];
    const float* fc_b  = (const float*)d_in[27];
    const float* out_w = (const float*)d_in[28];
    const float* out_b = (const float*)d_in[29];
    float* out = (float*)d_out;

    float *hbuf, *ybuf, *e0, *qkv, *abuf, *ffbuf, *vals;
    int* sel;
    cudaGetSymbolAddress((void**)&hbuf,  g_h);
    cudaGetSymbolAddress((void**)&ybuf,  g_y);
    cudaGetSymbolAddress((void**)&e0,    g_e0);
    cudaGetSymbolAddress((void**)&qkv,   g_qkv);
    cudaGetSymbolAddress((void**)&abuf,  g_a);
    cudaGetSymbolAddress((void**)&ffbuf, g_ff);
    cudaGetSymbolAddress((void**)&vals,  g_vals);
    cudaGetSymbolAddress((void**)&sel,   g_sel);

    // 1) embedding gather -> hbuf [S, E]
    embed_kernel<<<S_, E_>>>(x, emb, hbuf);

    // 2) three MoE blocks; ping-pong hbuf/ybuf
    const float* moe_in[3] = { hbuf, ybuf, hbuf };
    float*       moe_out_p[3] = { ybuf, hbuf, ybuf };
    int          moe_din[3] = { E_, H_, H_ };
    for (int i = 0; i < 3; i++) {
        int din = moe_din[i];
        gate_kernel<<<(S_ * 32) / 256, 256>>>(moe_in[i], din, moe_gw[i], moe_gb[i], vals, sel);
        // both experts in one z-batched launch
        gemm(moe_in[i], moe_ew[i], nullptr, e0, S_, H_, din, din, din, H_,
             0, 2, (long)S_ * H_, sel, (long)H_ * din);
        moe_combine<<<(S_ * H_) / 256, 256>>>(e0, e0 + (long)S_ * H_, moe_eb[i], vals, sel,
                                              moe_out_p[i]);
    }
    float* cur = ybuf;   // after moe2

    // 3) transformer layers
    for (int l = 0; l < NL_; l++) {
        gemm(cur, attn_in_w + (long)l * 3 * H_ * H_, attn_in_b + (long)l * 3 * H_,
             qkv, S_, 3 * H_, H_, H_, H_, 3 * H_, 0);
        flash_attn<<<dim3(S_ / 128, NH_), 256>>>(qkv, abuf);
        gemm(abuf, attn_out_w + (long)l * H_ * H_, attn_out_b + (long)l * H_,
             e0, S_, H_, H_, H_, H_, H_, 0);
        ln_kernel<<<S_, H_>>>(cur, e0, ln1_g + l * H_, ln1_b + l * H_);
        gemm(cur, ff1_w + (long)l * FF_ * H_, ff1_b + (long)l * FF_,
             ffbuf, S_, FF_, H_, H_, H_, FF_, 1);
        gemm(ffbuf, ff2_w + (long)l * H_ * FF_, ff2_b + (long)l * H_,
             e0, S_, H_, FF_, FF_, FF_, H_, 0);
        ln_kernel<<<S_, H_>>>(cur, e0, ln2_g + l * H_, ln2_b + l * H_);
    }

    // 4) fc + vocab logits + log_softmax
    gemm(cur, fc_w, fc_b, e0, S_, H_, H_, H_, H_, H_, 0);
    gemm(e0, out_w, out_b, out, S_, V_, H_, H_, H_, V_, 0);
    logsoftmax_kernel<<<S_, 256>>>(out);
}

// round 6
// speedup vs baseline: 8.7052x; 1.0698x over previous
#include <cuda_runtime.h>
#include <cuda_bf16.h>
#include <stdint.h>
#include <math.h>

#define S_   4096
#define E_   128
#define H_   256
#define NE_  4
#define NH_  4
#define HD_  64
#define FF_  2048
#define NL_  2
#define V_   10000
#define EPS_ 1e-5f
#define SCALE_ 0.125f   /* 1/sqrt(64) */

typedef __nv_bfloat16 bf16;

// ---------------- scratch (device globals; allocation-free) ----------------
__device__ float g_h  [S_ * H_];
__device__ float g_y  [S_ * H_];
__device__ float g_e0 [2 * S_ * H_];   // expert z-batch / residual temp
__device__ float g_vals[S_ * 2];
__device__ int   g_sel[2];

__device__ bf16 g_hbf [S_ * H_];
__device__ bf16 g_ybf [S_ * H_];
__device__ bf16 g_qkvbf[S_ * 3 * H_];
__device__ bf16 g_abf [S_ * H_];
__device__ bf16 g_ffbf[S_ * FF_];
__device__ bf16 g_fcbf[S_ * H_];

// bf16 weight mirrors
__device__ bf16 g_w_attn_in [NL_ * 3 * H_ * H_];
__device__ bf16 g_w_attn_out[NL_ * H_ * H_];
__device__ bf16 g_w_ff1     [NL_ * FF_ * H_];
__device__ bf16 g_w_ff2     [NL_ * H_ * FF_];
__device__ bf16 g_w_fc      [H_ * H_];
__device__ bf16 g_w_out     [V_ * H_];
__device__ bf16 g_w_moe0    [NE_ * H_ * E_];
__device__ bf16 g_w_moe1    [NE_ * H_ * H_];
__device__ bf16 g_w_moe2    [NE_ * H_ * H_];

// ---------------- fp32 -> bf16 convert (n % 4 == 0) ----------------
__global__ void f2bf_kernel(const float* __restrict__ s, bf16* __restrict__ d, int n) {
    int i = (blockIdx.x * blockDim.x + threadIdx.x) * 4;
    if (i >= n) return;
    float4 v = *(const float4*)(s + i);
    __nv_bfloat162 p0 = __float22bfloat162_rn(make_float2(v.x, v.y));
    __nv_bfloat162 p1 = __float22bfloat162_rn(make_float2(v.z, v.w));
    *(__nv_bfloat162*)(d + i)     = p0;
    *(__nv_bfloat162*)(d + i + 2) = p1;
}

// ---------------- embed gather (dual write) ----------------
__global__ void embed_kernel(const int* __restrict__ x, const float* __restrict__ emb,
                             float* __restrict__ out, bf16* __restrict__ outb) {
    int s = blockIdx.x;
    int d = threadIdx.x;           // E_ = 128 threads
    float v = emb[(long)x[s] * E_ + d];
    out[s * E_ + d]  = v;
    outb[s * E_ + d] = __float2bfloat16_rn(v);
}

// ---------------- MoE gate ----------------
__global__ void gate_kernel(const float* __restrict__ x, int din,
                            const float* __restrict__ gw, const float* __restrict__ gb,
                            float* __restrict__ vals, int* __restrict__ sel) {
    int gtid = blockIdx.x * blockDim.x + threadIdx.x;
    int tok  = gtid >> 5;
    int lane = gtid & 31;
    if (tok >= S_) return;
    const float* xr = x + (long)tok * din;
    float p0 = 0.f, p1 = 0.f, p2 = 0.f, p3 = 0.f;
    for (int d = lane; d < din; d += 32) {
        float xv = xr[d];
        p0 += xv * gw[0 * din + d];
        p1 += xv * gw[1 * din + d];
        p2 += xv * gw[2 * din + d];
        p3 += xv * gw[3 * din + d];
    }
    #pragma unroll
    for (int o = 16; o > 0; o >>= 1) {
        p0 += __shfl_xor_sync(0xffffffffu, p0, o);
        p1 += __shfl_xor_sync(0xffffffffu, p1, o);
        p2 += __shfl_xor_sync(0xffffffffu, p2, o);
        p3 += __shfl_xor_sync(0xffffffffu, p3, o);
    }
    if (lane == 0) {
        float sc[4] = { p0 + gb[0], p1 + gb[1], p2 + gb[2], p3 + gb[3] };
        float m = fmaxf(fmaxf(sc[0], sc[1]), fmaxf(sc[2], sc[3]));
        float e[4]; float sum = 0.f;
        #pragma unroll
        for (int i = 0; i < 4; i++) { e[i] = expf(sc[i] - m); sum += e[i]; }
        float inv = 1.f / sum;
        #pragma unroll
        for (int i = 0; i < 4; i++) e[i] *= inv;
        int i0 = 0;
        #pragma unroll
        for (int i = 1; i < 4; i++) if (e[i] > e[i0]) i0 = i;
        int i1 = -1;
        #pragma unroll
        for (int i = 0; i < 4; i++) {
            if (i == i0) continue;
            if (i1 < 0 || e[i] > e[i1]) i1 = i;
        }
        vals[tok * 2 + 0] = e[i0];
        vals[tok * 2 + 1] = e[i1];
        if (tok == 0) { sel[0] = i0; sel[1] = i1; }
    }
}

// ---------------- MoE combine (dual write) ----------------
__global__ void moe_combine(const float* __restrict__ e0, const float* __restrict__ e1,
                            const float* __restrict__ eb, const float* __restrict__ vals,
                            const int* __restrict__ sel, float* __restrict__ out,
                            bf16* __restrict__ outb) {
    long i = (long)blockIdx.x * blockDim.x + threadIdx.x;
    if (i >= (long)S_ * H_) return;
    int s = (int)(i / H_);
    int h = (int)(i % H_);
    float b0 = eb[sel[0] * H_ + h];
    float b1 = eb[sel[1] * H_ + h];
    float v = vals[s * 2] * (e0[i] + b0) + vals[s * 2 + 1] * (e1[i] + b1);
    out[i]  = v;
    outb[i] = __float2bfloat16_rn(v);
}

#define MMA_BF16(ACC, A0, A1, A2, A3, B0, B1)                                  \
    asm volatile(                                                              \
        "mma.sync.aligned.m16n8k16.row.col.f32.bf16.bf16.f32 "                 \
        "{%0,%1,%2,%3}, {%4,%5,%6,%7}, {%8,%9}, {%0,%1,%2,%3};\n"              \
        : "+f"((ACC)[0]), "+f"((ACC)[1]), "+f"((ACC)[2]), "+f"((ACC)[3])       \
        : "r"(A0), "r"(A1), "r"(A2), "r"(A3), "r"(B0), "r"(B1))

static __device__ __forceinline__ unsigned packbf(float x, float y) {
    __nv_bfloat162 p = __float22bfloat162_rn(make_float2(x, y));
    return *(unsigned*)&p;
}

static __device__ __forceinline__ void cp16(unsigned dst, const void* src, int sz) {
    asm volatile("cp.async.ca.shared.global [%0], [%1], 16, %2;\n"
                 :: "r"(dst), "l"(src), "r"(sz));
}

// ---------------- bf16 GEMM, cp.async 3-stage pipeline ----------------
// C[M,N] = A * B^T + bias (+relu). A: bf16 [M,K] k-contig (lda). B row n: bf16 k-contig (ldb).
// Output: fp32 C if Cb==nullptr, else bf16 Cb. Expert batching via sel/selStride/batchC.
// M % 128 == 0, K % 32 == 0, N even.
__global__ __launch_bounds__(256, 2)
void gemm_bf(const bf16* __restrict__ A, const bf16* __restrict__ B,
             const float* __restrict__ bias, float* __restrict__ C, bf16* __restrict__ Cb,
             int M, int N, int K, int lda, int ldb, int ldc,
             long batchC, int do_relu, const int* __restrict__ sel, long selStride) {
    constexpr int BM = 128, BN = 64, BK = 32, PAD = 8, ST = 3;
    constexpr int RS = BK + PAD;         // 40 elts (80B) row stride
    constexpr int ROWS = BM + BN;        // 192 rows per stage
    __shared__ __align__(16) bf16 sm[ST * ROWS * RS];

    if (sel) B += (long)sel[blockIdx.z] * selStride;
    long zoff = (long)blockIdx.z * batchC;

    int bm = blockIdx.y * BM;
    int bn = blockIdx.x * BN;
    int tid  = threadIdx.x;
    int lane = tid & 31;
    int wid  = tid >> 5;
    int warpM = (wid & 3) * 32;
    int warpN = (wid >> 2) * 32;
    unsigned sbase = (unsigned)__cvta_generic_to_shared(sm);

    auto issue = [&](int stage, int k0) {
        #pragma unroll
        for (int t = 0; t < 2; t++) {              // A tile: 512 x 16B
            int idx = tid + t * 256;
            int row = idx >> 2, c = idx & 3;
            const void* src = A + (long)(bm + row) * lda + k0 + c * 8;
            unsigned dst = sbase + (unsigned)(((stage * ROWS + row) * RS + c * 8) * 2);
            cp16(dst, src, 16);
        }
        {                                          // B tile: 256 x 16B
            int row = tid >> 2, c = tid & 3;
            int gn = bn + row;
            const void* src = B + (long)(gn < N ? gn : 0) * ldb + k0 + c * 8;
            unsigned dst = sbase + (unsigned)(((stage * ROWS + BM + row) * RS + c * 8) * 2);
            cp16(dst, src, gn < N ? 16 : 0);
        }
        asm volatile("cp.async.commit_group;\n");
    };

    float acc[2][4][4];
    #pragma unroll
    for (int mt = 0; mt < 2; mt++)
        #pragma unroll
        for (int nt = 0; nt < 4; nt++)
            #pragma unroll
            for (int r = 0; r < 4; r++) acc[mt][nt][r] = 0.f;

    int g = lane >> 2;
    int q = lane & 3;
    int ntiles = K / BK;

    issue(0, 0);
    issue(1, BK);

    for (int t = 0; t < ntiles; t++) {
        asm volatile("cp.async.wait_group 1;\n");
        __syncthreads();
        if (t + 2 < ntiles) issue((t + 2) % ST, (t + 2) * BK);

        const bf16* As = sm + (t % ST) * ROWS * RS;
        const bf16* Bs = As + BM * RS;
        #pragma unroll
        for (int ks = 0; ks < BK; ks += 16) {
            unsigned a[2][4], b[4][2];
            int ac = ks + q * 2;
            #pragma unroll
            for (int mt = 0; mt < 2; mt++) {
                int r = warpM + mt * 16 + g;
                a[mt][0] = *(const unsigned*)&As[r * RS + ac];
                a[mt][1] = *(const unsigned*)&As[(r + 8) * RS + ac];
                a[mt][2] = *(const unsigned*)&As[r * RS + ac + 8];
                a[mt][3] = *(const unsigned*)&As[(r + 8) * RS + ac + 8];
            }
            #pragma unroll
            for (int nt = 0; nt < 4; nt++) {
                int nr = warpN + nt * 8 + g;
                b[nt][0] = *(const unsigned*)&Bs[nr * RS + ac];
                b[nt][1] = *(const unsigned*)&Bs[nr * RS + ac + 8];
            }
            #pragma unroll
            for (int mt = 0; mt < 2; mt++)
                #pragma unroll
                for (int nt = 0; nt < 4; nt++)
                    MMA_BF16(acc[mt][nt], a[mt][0], a[mt][1], a[mt][2], a[mt][3],
                             b[nt][0], b[nt][1]);
        }
    }

    #pragma unroll
    for (int mt = 0; mt < 2; mt++) {
        int row0 = bm + warpM + mt * 16 + g;
        #pragma unroll
        for (int nt = 0; nt < 4; nt++) {
            int col = bn + warpN + nt * 8 + q * 2;
            if (col >= N) continue;
            float b0 = bias ? bias[col]     : 0.f;
            float b1 = bias ? bias[col + 1] : 0.f;
            float v00 = acc[mt][nt][0] + b0;
            float v01 = acc[mt][nt][1] + b1;
            float v10 = acc[mt][nt][2] + b0;
            float v11 = acc[mt][nt][3] + b1;
            if (do_relu) {
                v00 = fmaxf(v00, 0.f); v01 = fmaxf(v01, 0.f);
                v10 = fmaxf(v10, 0.f); v11 = fmaxf(v11, 0.f);
            }
            if (Cb) {
                *(unsigned*)(Cb + zoff + (long)row0 * ldc + col)       = packbf(v00, v01);
                *(unsigned*)(Cb + zoff + (long)(row0 + 8) * ldc + col) = packbf(v10, v11);
            } else {
                *(float2*)(C + zoff + (long)row0 * ldc + col)       = make_float2(v00, v01);
                *(float2*)(C + zoff + (long)(row0 + 8) * ldc + col) = make_float2(v10, v11);
            }
        }
    }
}

// ---------------- fused flash attention (bf16 qkv in, bf16 out) ----------------
// qkv: [S, 3H] bf16. o: [S, H] bf16. grid (S/128, NH), 256 threads.
__global__ __launch_bounds__(256)
void flash_attn(const bf16* __restrict__ qkv, bf16* __restrict__ o) {
    constexpr int BM = 128, BN = 64, D = HD_, PD = 8;
    __shared__ __align__(16) bf16 Qs[BM][D + PD];
    __shared__ __align__(16) bf16 Ks[BN][D + PD];
    __shared__ __align__(16) bf16 Vs[D][BN + PD];

    int h  = blockIdx.y;
    int bm = blockIdx.x * BM;
    int tid = threadIdx.x;
    int lane = tid & 31;
    int w = tid >> 5;
    int g = lane >> 2;
    int q = lane & 3;

    const bf16* Qp = qkv + h * HD_;
    const bf16* Kp = qkv + H_ + h * HD_;
    const bf16* Vp = qkv + 2 * H_ + h * HD_;

    // Q tile: 128 rows x 8 chunks of 8 bf16
    #pragma unroll
    for (int i = 0; i < 4; i++) {
        int idx = tid + i * 256;
        int row = idx >> 3;
        int c   = idx & 7;
        uint4 v = *(const uint4*)(Qp + (long)(bm + row) * (3 * H_) + c * 8);
        *(uint4*)&Qs[row][c * 8] = v;
    }

    float m0 = -1e30f, m1 = -1e30f, l0 = 0.f, l1 = 0.f;
    float out[8][4];
    #pragma unroll
    for (int ot = 0; ot < 8; ot++)
        #pragma unroll
        for (int r = 0; r < 4; r++) out[ot][r] = 0.f;

    int rowA = w * 16 + g;

    for (int j = 0; j < S_ / BN; j++) {
        __syncthreads();
        #pragma unroll
        for (int i = 0; i < 2; i++) {
            int idx = tid + i * 256;
            int key = idx >> 3;
            int c   = idx & 7;
            uint4 v = *(const uint4*)(Kp + (long)(j * BN + key) * (3 * H_) + c * 8);
            *(uint4*)&Ks[key][c * 8] = v;
        }
        #pragma unroll
        for (int i = 0; i < 2; i++) {
            int idx = tid + i * 256;
            int key = idx >> 3;
            int c   = idx & 7;
            uint4 v = *(const uint4*)(Vp + (long)(j * BN + key) * (3 * H_) + c * 8);
            __nv_bfloat162 p0 = *(__nv_bfloat162*)&v.x;
            __nv_bfloat162 p1 = *(__nv_bfloat162*)&v.y;
            __nv_bfloat162 p2 = *(__nv_bfloat162*)&v.z;
            __nv_bfloat162 p3 = *(__nv_bfloat162*)&v.w;
            int d0 = c * 8;
            Vs[d0 + 0][key] = p0.x; Vs[d0 + 1][key] = p0.y;
            Vs[d0 + 2][key] = p1.x; Vs[d0 + 3][key] = p1.y;
            Vs[d0 + 4][key] = p2.x; Vs[d0 + 5][key] = p2.y;
            Vs[d0 + 6][key] = p3.x; Vs[d0 + 7][key] = p3.y;
        }
        __syncthreads();

        float acc[8][4];
        #pragma unroll
        for (int nt = 0; nt < 8; nt++)
            #pragma unroll
            for (int r = 0; r < 4; r++) acc[nt][r] = 0.f;
        #pragma unroll
        for (int kc = 0; kc < 4; kc++) {
            int ac = kc * 16 + q * 2;
            unsigned a0 = *(const unsigned*)&Qs[rowA][ac];
            unsigned a1 = *(const unsigned*)&Qs[rowA + 8][ac];
            unsigned a2 = *(const unsigned*)&Qs[rowA][ac + 8];
            unsigned a3 = *(const unsigned*)&Qs[rowA + 8][ac + 8];
            #pragma unroll
            for (int nt = 0; nt < 8; nt++) {
                unsigned b0 = *(const unsigned*)&Ks[nt * 8 + g][ac];
                unsigned b1 = *(const unsigned*)&Ks[nt * 8 + g][ac + 8];
                MMA_BF16(acc[nt], a0, a1, a2, a3, b0, b1);
            }
        }

        float tm0 = -1e30f, tm1 = -1e30f;
        #pragma unroll
        for (int nt = 0; nt < 8; nt++) {
            acc[nt][0] *= SCALE_; acc[nt][1] *= SCALE_;
            acc[nt][2] *= SCALE_; acc[nt][3] *= SCALE_;
            tm0 = fmaxf(tm0, fmaxf(acc[nt][0], acc[nt][1]));
            tm1 = fmaxf(tm1, fmaxf(acc[nt][2], acc[nt][3]));
        }
        tm0 = fmaxf(tm0, __shfl_xor_sync(0xffffffffu, tm0, 1));
        tm0 = fmaxf(tm0, __shfl_xor_sync(0xffffffffu, tm0, 2));
        tm1 = fmaxf(tm1, __shfl_xor_sync(0xffffffffu, tm1, 1));
        tm1 = fmaxf(tm1, __shfl_xor_sync(0xffffffffu, tm1, 2));
        float mn0 = fmaxf(m0, tm0), mn1 = fmaxf(m1, tm1);
        float corr0 = __expf(m0 - mn0), corr1 = __expf(m1 - mn1);
        float s0 = 0.f, s1 = 0.f;
        #pragma unroll
        for (int nt = 0; nt < 8; nt++) {
            acc[nt][0] = __expf(acc[nt][0] - mn0);
            acc[nt][1] = __expf(acc[nt][1] - mn0);
            acc[nt][2] = __expf(acc[nt][2] - mn1);
            acc[nt][3] = __expf(acc[nt][3] - mn1);
            s0 += acc[nt][0] + acc[nt][1];
            s1 += acc[nt][2] + acc[nt][3];
        }
        m0 = mn0; m1 = mn1;
        l0 = l0 * corr0 + s0;
        l1 = l1 * corr1 + s1;
        #pragma unroll
        for (int ot = 0; ot < 8; ot++) {
            out[ot][0] *= corr0; out[ot][1] *= corr0;
            out[ot][2] *= corr1; out[ot][3] *= corr1;
        }

        #pragma unroll
        for (int kc = 0; kc < 4; kc++) {
            unsigned a0 = packbf(acc[2 * kc][0],     acc[2 * kc][1]);
            unsigned a1 = packbf(acc[2 * kc][2],     acc[2 * kc][3]);
            unsigned a2 = packbf(acc[2 * kc + 1][0], acc[2 * kc + 1][1]);
            unsigned a3 = packbf(acc[2 * kc + 1][2], acc[2 * kc + 1][3]);
            int kb = kc * 16 + q * 2;
            #pragma unroll
            for (int ot = 0; ot < 8; ot++) {
                unsigned b0 = *(const unsigned*)&Vs[ot * 8 + g][kb];
                unsigned b1 = *(const unsigned*)&Vs[ot * 8 + g][kb + 8];
                MMA_BF16(out[ot], a0, a1, a2, a3, b0, b1);
            }
        }
    }

    l0 += __shfl_xor_sync(0xffffffffu, l0, 1);
    l0 += __shfl_xor_sync(0xffffffffu, l0, 2);
    l1 += __shfl_xor_sync(0xffffffffu, l1, 1);
    l1 += __shfl_xor_sync(0xffffffffu, l1, 2);
    float inv0 = 1.f / l0, inv1 = 1.f / l1;
    int row0 = bm + w * 16 + g;
    #pragma unroll
    for (int ot = 0; ot < 8; ot++) {
        int col = h * HD_ + ot * 8 + q * 2;
        *(unsigned*)(o + (long)row0 * H_ + col) =
            packbf(out[ot][0] * inv0, out[ot][1] * inv0);
        *(unsigned*)(o + (long)(row0 + 8) * H_ + col) =
            packbf(out[ot][2] * inv1, out[ot][3] * inv1);
    }
}

// ---------------- residual add + LayerNorm (dual write) ----------------
__global__ void ln_kernel(float* __restrict__ h, const float* __restrict__ t,
                          const float* __restrict__ g, const float* __restrict__ b,
                          bf16* __restrict__ hb) {
    __shared__ float red[H_];
    int s = blockIdx.x;
    int d = threadIdx.x;
    float v = h[s * H_ + d] + t[s * H_ + d];
    red[d] = v;
    __syncthreads();
    for (int o = H_ / 2; o > 0; o >>= 1) {
        if (d < o) red[d] += red[d + o];
        __syncthreads();
    }
    float m = red[0] * (1.f / H_);
    __syncthreads();
    float c = v - m;
    red[d] = c * c;
    __syncthreads();
    for (int o = H_ / 2; o > 0; o >>= 1) {
        if (d < o) red[d] += red[d + o];
        __syncthreads();
    }
    float var = red[0] * (1.f / H_);
    float r = c * rsqrtf(var + EPS_) * g[d] + b[d];
    h[s * H_ + d]  = r;
    hb[s * H_ + d] = __float2bfloat16_rn(r);
}

// ---------------- final log_softmax over vocab rows (len 10000), in place ----------------
__global__ void logsoftmax_kernel(float* __restrict__ out) {
    __shared__ float red[256];
    float* p = out + (long)blockIdx.x * V_;
    int t = threadIdx.x;
    float loc[40];
    float m = -1e30f;
    #pragma unroll
    for (int i = 0; i < 40; i++) {
        int c = t + i * 256;
        loc[i] = (c < V_) ? p[c] : -1e30f;
        m = fmaxf(m, loc[i]);
    }
    red[t] = m;
    __syncthreads();
    for (int o = 128; o > 0; o >>= 1) {
        if (t < o) red[t] = fmaxf(red[t], red[t + o]);
        __syncthreads();
    }
    m = red[0];
    __syncthreads();
    float sum = 0.f;
    #pragma unroll
    for (int i = 0; i < 40; i++) {
        int c = t + i * 256;
        if (c < V_) sum += expf(loc[i] - m);
    }
    red[t] = sum;
    __syncthreads();
    for (int o = 128; o > 0; o >>= 1) {
        if (t < o) red[t] += red[t + o];
        __syncthreads();
    }
    float lse = m + logf(red[0]);
    #pragma unroll
    for (int i = 0; i < 40; i++) {
        int c = t + i * 256;
        if (c < V_) p[c] = loc[i] - lse;
    }
}

// ---------------- host side ----------------
static inline void gemm(const bf16* A, const bf16* B, const float* bias,
                        float* C, bf16* Cb,
                        int M, int N, int K, int lda, int ldb, int ldc,
                        int relu,
                        int Z = 1, long batchC = 0,
                        const int* sel = nullptr, long selStride = 0) {
    dim3 grid((N + 63) / 64, M / 128, Z);
    gemm_bf<<<grid, 256>>>(A, B, bias, C, Cb, M, N, K, lda, ldb, ldc,
                           batchC, relu, sel, selStride);
}

static inline void f2bf(const float* s, bf16* d, int n) {
    f2bf_kernel<<<(n / 4 + 255) / 256, 256>>>(s, d, n);
}

extern "C" void kernel_launch(void* const* d_in, const int* in_sizes, int n_in,
                              void* d_out, int out_size) {
    const int*   x         = (const int*)d_in[0];
    const float* emb       = (const float*)d_in[1];
    const float* moe_gw[3] = { (const float*)d_in[2], (const float*)d_in[6], (const float*)d_in[10] };
    const float* moe_gb[3] = { (const float*)d_in[3], (const float*)d_in[7], (const float*)d_in[11] };
    const float* moe_ew[3] = { (const float*)d_in[4], (const float*)d_in[8], (const float*)d_in[12] };
    const float* moe_eb[3] = { (const float*)d_in[5], (const float*)d_in[9], (const float*)d_in[13] };
    const float* attn_in_w  = (const float*)d_in[14];
    const float* attn_in_b  = (const float*)d_in[15];
    const float* attn_out_w = (const float*)d_in[16];
    const float* attn_out_b = (const float*)d_in[17];
    const float* ln1_g = (const float*)d_in[18];
    const float* ln1_b = (const float*)d_in[19];
    const float* ln2_g = (const float*)d_in[20];
    const float* ln2_b = (const float*)d_in[21];
    const float* ff1_w = (const float*)d_in[22];
    const float* ff1_b = (const float*)d_in[23];
    const float* ff2_w = (const float*)d_in[24];
    const float* ff2_b = (const float*)d_in[25];
    const float* fc_w  = (const float*)d_in[26];
    const float* fc_b  = (const float*)d_in[27];
    const float* out_w = (const float*)d_in[28];
    const float* out_b = (const float*)d_in[29];
    float* out = (float*)d_out;

    float *hbuf, *ybuf, *e0, *vals;
    int* sel;
    bf16 *hbf, *ybf, *qkvbf, *abf, *ffbf, *fcbf;
    bf16 *w_ain, *w_aout, *w_ff1, *w_ff2, *w_fc, *w_out, *w_m0, *w_m1, *w_m2;
    cudaGetSymbolAddress((void**)&hbuf, g_h);
    cudaGetSymbolAddress((void**)&ybuf, g_y);
    cudaGetSymbolAddress((void**)&e0,   g_e0);
    cudaGetSymbolAddress((void**)&vals, g_vals);
    cudaGetSymbolAddress((void**)&sel,  g_sel);
    cudaGetSymbolAddress((void**)&hbf,   g_hbf);
    cudaGetSymbolAddress((void**)&ybf,   g_ybf);
    cudaGetSymbolAddress((void**)&qkvbf, g_qkvbf);
    cudaGetSymbolAddress((void**)&abf,   g_abf);
    cudaGetSymbolAddress((void**)&ffbf,  g_ffbf);
    cudaGetSymbolAddress((void**)&fcbf,  g_fcbf);
    cudaGetSymbolAddress((void**)&w_ain,  g_w_attn_in);
    cudaGetSymbolAddress((void**)&w_aout, g_w_attn_out);
    cudaGetSymbolAddress((void**)&w_ff1,  g_w_ff1);
    cudaGetSymbolAddress((void**)&w_ff2,  g_w_ff2);
    cudaGetSymbolAddress((void**)&w_fc,   g_w_fc);
    cudaGetSymbolAddress((void**)&w_out,  g_w_out);
    cudaGetSymbolAddress((void**)&w_m0,   g_w_moe0);
    cudaGetSymbolAddress((void**)&w_m1,   g_w_moe1);
    cudaGetSymbolAddress((void**)&w_m2,   g_w_moe2);

    // 0) weight conversion (once per launch)
    f2bf(attn_in_w,  w_ain,  NL_ * 3 * H_ * H_);
    f2bf(attn_out_w, w_aout, NL_ * H_ * H_);
    f2bf(ff1_w,      w_ff1,  NL_ * FF_ * H_);
    f2bf(ff2_w,      w_ff2,  NL_ * H_ * FF_);
    f2bf(fc_w,       w_fc,   H_ * H_);
    f2bf(out_w,      w_out,  V_ * H_);
    f2bf(moe_ew[0],  w_m0,   NE_ * H_ * E_);
    f2bf(moe_ew[1],  w_m1,   NE_ * H_ * H_);
    f2bf(moe_ew[2],  w_m2,   NE_ * H_ * H_);

    // 1) embedding gather
    embed_kernel<<<S_, E_>>>(x, emb, hbuf, hbf);

    // 2) three MoE blocks; ping-pong (fp32 + bf16 views)
    const float* moe_in_f[3]  = { hbuf, ybuf, hbuf };
    const bf16*  moe_in_b[3]  = { hbf,  ybf,  hbf  };
    float*       moe_out_f[3] = { ybuf, hbuf, ybuf };
    bf16*        moe_out_b[3] = { ybf,  hbf,  ybf  };
    const bf16*  moe_w[3]     = { w_m0, w_m1, w_m2 };
    int          moe_din[3]   = { E_, H_, H_ };
    for (int i = 0; i < 3; i++) {
        int din = moe_din[i];
        gate_kernel<<<(S_ * 32) / 256, 256>>>(moe_in_f[i], din, moe_gw[i], moe_gb[i], vals, sel);
        gemm(moe_in_b[i], moe_w[i], nullptr, e0, nullptr, S_, H_, din, din, din, H_,
             0, 2, (long)S_ * H_, sel, (long)H_ * din);
        moe_combine<<<(S_ * H_) / 256, 256>>>(e0, e0 + (long)S_ * H_, moe_eb[i], vals, sel,
                                              moe_out_f[i], moe_out_b[i]);
    }
    float* cur  = ybuf;
    bf16*  curb = ybf;

    // 3) transformer layers
    for (int l = 0; l < NL_; l++) {
        gemm(curb, w_ain + (long)l * 3 * H_ * H_, attn_in_b + (long)l * 3 * H_,
             nullptr, qkvbf, S_, 3 * H_, H_, H_, H_, 3 * H_, 0);
        flash_attn<<<dim3(S_ / 128, NH_), 256>>>(qkvbf, abf);
        gemm(abf, w_aout + (long)l * H_ * H_, attn_out_b + (long)l * H_,
             e0, nullptr, S_, H_, H_, H_, H_, H_, 0);
        ln_kernel<<<S_, H_>>>(cur, e0, ln1_g + l * H_, ln1_b + l * H_, curb);
        gemm(curb, w_ff1 + (long)l * FF_ * H_, ff1_b + (long)l * FF_,
             nullptr, ffbf, S_, FF_, H_, H_, H_, FF_, 1);
        gemm(ffbf, w_ff2 + (long)l * H_ * FF_, ff2_b + (long)l * H_,
             e0, nullptr, S_, H_, FF_, FF_, FF_, H_, 0);
        ln_kernel<<<S_, H_>>>(cur, e0, ln2_g + l * H_, ln2_b + l * H_, curb);
    }

    // 4) fc + vocab logits + log_softmax
    gemm(curb, w_fc, fc_b, nullptr, fcbf, S_, H_, H_, H_, H_, H_, 0);
    gemm(fcbf, w_out, out_b, out, nullptr, S_, V_, H_, H_, H_, V_, 0);
    logsoftmax_kernel<<<S_, 256>>>(out);
}

// round 7
// speedup vs baseline: 9.9104x; 1.1385x over previous
#include <cuda_runtime.h>
#include <cuda_bf16.h>
#include <stdint.h>
#include <math.h>

#define S_   4096
#define E_   128
#define H_   256
#define NE_  4
#define NH_  4
#define HD_  64
#define FF_  2048
#define NL_  2
#define V_   10000
#define EPS_ 1e-5f
#define SCALE_ 0.125f   /* 1/sqrt(64) */

typedef __nv_bfloat16 bf16;

// ---------------- scratch (device globals; allocation-free) ----------------
__device__ float g_h  [S_ * H_];
__device__ float g_y  [S_ * H_];
__device__ float g_e0 [2 * S_ * H_];   // expert z-batch / residual temp
__device__ float g_vals[S_ * 2];
__device__ int   g_sel[2];

__device__ bf16 g_hbf [S_ * H_];
__device__ bf16 g_ybf [S_ * H_];
__device__ bf16 g_qkvbf[S_ * 3 * H_];
__device__ bf16 g_abf [S_ * H_];
__device__ bf16 g_ffbf[S_ * FF_];
__device__ bf16 g_fcbf[S_ * H_];
__device__ bf16 g_logbf[S_ * V_];      // bf16 logits (80 MB)

// bf16 weight mirrors
__device__ bf16 g_w_attn_in [NL_ * 3 * H_ * H_];
__device__ bf16 g_w_attn_out[NL_ * H_ * H_];
__device__ bf16 g_w_ff1     [NL_ * FF_ * H_];
__device__ bf16 g_w_ff2     [NL_ * H_ * FF_];
__device__ bf16 g_w_fc      [H_ * H_];
__device__ bf16 g_w_out     [V_ * H_];
__device__ bf16 g_w_moe0    [NE_ * H_ * E_];
__device__ bf16 g_w_moe1    [NE_ * H_ * H_];
__device__ bf16 g_w_moe2    [NE_ * H_ * H_];

// ---------------- fp32 -> bf16 convert (n % 4 == 0) ----------------
__global__ void f2bf_kernel(const float* __restrict__ s, bf16* __restrict__ d, int n) {
    int i = (blockIdx.x * blockDim.x + threadIdx.x) * 4;
    if (i >= n) return;
    float4 v = *(const float4*)(s + i);
    __nv_bfloat162 p0 = __float22bfloat162_rn(make_float2(v.x, v.y));
    __nv_bfloat162 p1 = __float22bfloat162_rn(make_float2(v.z, v.w));
    *(__nv_bfloat162*)(d + i)     = p0;
    *(__nv_bfloat162*)(d + i + 2) = p1;
}

// ---------------- embed gather (dual write) ----------------
__global__ void embed_kernel(const int* __restrict__ x, const float* __restrict__ emb,
                             float* __restrict__ out, bf16* __restrict__ outb) {
    int s = blockIdx.x;
    int d = threadIdx.x;           // E_ = 128 threads
    float v = emb[(long)x[s] * E_ + d];
    out[s * E_ + d]  = v;
    outb[s * E_ + d] = __float2bfloat16_rn(v);
}

// ---------------- MoE gate ----------------
__global__ void gate_kernel(const float* __restrict__ x, int din,
                            const float* __restrict__ gw, const float* __restrict__ gb,
                            float* __restrict__ vals, int* __restrict__ sel) {
    int gtid = blockIdx.x * blockDim.x + threadIdx.x;
    int tok  = gtid >> 5;
    int lane = gtid & 31;
    if (tok >= S_) return;
    const float* xr = x + (long)tok * din;
    float p0 = 0.f, p1 = 0.f, p2 = 0.f, p3 = 0.f;
    for (int d = lane; d < din; d += 32) {
        float xv = xr[d];
        p0 += xv * gw[0 * din + d];
        p1 += xv * gw[1 * din + d];
        p2 += xv * gw[2 * din + d];
        p3 += xv * gw[3 * din + d];
    }
    #pragma unroll
    for (int o = 16; o > 0; o >>= 1) {
        p0 += __shfl_xor_sync(0xffffffffu, p0, o);
        p1 += __shfl_xor_sync(0xffffffffu, p1, o);
        p2 += __shfl_xor_sync(0xffffffffu, p2, o);
        p3 += __shfl_xor_sync(0xffffffffu, p3, o);
    }
    if (lane == 0) {
        float sc[4] = { p0 + gb[0], p1 + gb[1], p2 + gb[2], p3 + gb[3] };
        float m = fmaxf(fmaxf(sc[0], sc[1]), fmaxf(sc[2], sc[3]));
        float e[4]; float sum = 0.f;
        #pragma unroll
        for (int i = 0; i < 4; i++) { e[i] = expf(sc[i] - m); sum += e[i]; }
        float inv = 1.f / sum;
        #pragma unroll
        for (int i = 0; i < 4; i++) e[i] *= inv;
        int i0 = 0;
        #pragma unroll
        for (int i = 1; i < 4; i++) if (e[i] > e[i0]) i0 = i;
        int i1 = -1;
        #pragma unroll
        for (int i = 0; i < 4; i++) {
            if (i == i0) continue;
            if (i1 < 0 || e[i] > e[i1]) i1 = i;
        }
        vals[tok * 2 + 0] = e[i0];
        vals[tok * 2 + 1] = e[i1];
        if (tok == 0) { sel[0] = i0; sel[1] = i1; }
    }
}

// ---------------- MoE combine (dual write) ----------------
__global__ void moe_combine(const float* __restrict__ e0, const float* __restrict__ e1,
                            const float* __restrict__ eb, const float* __restrict__ vals,
                            const int* __restrict__ sel, float* __restrict__ out,
                            bf16* __restrict__ outb) {
    long i = (long)blockIdx.x * blockDim.x + threadIdx.x;
    if (i >= (long)S_ * H_) return;
    int s = (int)(i / H_);
    int h = (int)(i % H_);
    float b0 = eb[sel[0] * H_ + h];
    float b1 = eb[sel[1] * H_ + h];
    float v = vals[s * 2] * (e0[i] + b0) + vals[s * 2 + 1] * (e1[i] + b1);
    out[i]  = v;
    outb[i] = __float2bfloat16_rn(v);
}

#define MMA_BF16(ACC, A0, A1, A2, A3, B0, B1)                                  \
    asm volatile(                                                              \
        "mma.sync.aligned.m16n8k16.row.col.f32.bf16.bf16.f32 "                 \
        "{%0,%1,%2,%3}, {%4,%5,%6,%7}, {%8,%9}, {%0,%1,%2,%3};\n"              \
        : "+f"((ACC)[0]), "+f"((ACC)[1]), "+f"((ACC)[2]), "+f"((ACC)[3])       \
        : "r"(A0), "r"(A1), "r"(A2), "r"(A3), "r"(B0), "r"(B1))

static __device__ __forceinline__ unsigned packbf(float x, float y) {
    __nv_bfloat162 p = __float22bfloat162_rn(make_float2(x, y));
    return *(unsigned*)&p;
}

static __device__ __forceinline__ void cp16(unsigned dst, const void* src, int sz) {
    asm volatile("cp.async.ca.shared.global [%0], [%1], 16, %2;\n"
                 :: "r"(dst), "l"(src), "r"(sz));
}

// ---------------- bf16 GEMM, cp.async pipeline, templated tile width ----------------
// C[M,N] = A * B^T + bias (+relu). A bf16 [M,K] k-contig (lda). B row n: bf16 k-contig (ldb).
// Output: fp32 C if Cb==nullptr, else bf16 Cb. Expert batching via sel/selStride/batchC.
// M % 128 == 0, K % 32 == 0.
template <int BN, int ST>
__global__ __launch_bounds__(256, 2)
void gemm_bf(const bf16* __restrict__ A, const bf16* __restrict__ B,
             const float* __restrict__ bias, float* __restrict__ C, bf16* __restrict__ Cb,
             int M, int N, int K, int lda, int ldb, int ldc,
             long batchC, int do_relu, const int* __restrict__ sel, long selStride) {
    constexpr int BM = 128, BK = 32, PAD = 8;
    constexpr int RS = BK + PAD;
    constexpr int ROWS = BM + BN;
    constexpr int NT = BN / 16;          // 8-col frags per warp
    __shared__ __align__(16) bf16 sm[ST * ROWS * RS];

    if (sel) B += (long)sel[blockIdx.z] * selStride;
    long zoff = (long)blockIdx.z * batchC;

    int bm = blockIdx.y * BM;
    int bn = blockIdx.x * BN;
    int tid  = threadIdx.x;
    int lane = tid & 31;
    int wid  = tid >> 5;
    int warpM = (wid & 3) * 32;
    int warpN = (wid >> 2) * (BN / 2);
    unsigned sbase = (unsigned)__cvta_generic_to_shared(sm);

    auto issue = [&](int stage, int k0) {
        #pragma unroll
        for (int t = 0; t < BM * 4 / 256; t++) {      // A tile
            int idx = tid + t * 256;
            int row = idx >> 2, c = idx & 3;
            const void* src = A + (long)(bm + row) * lda + k0 + c * 8;
            unsigned dst = sbase + (unsigned)(((stage * ROWS + row) * RS + c * 8) * 2);
            cp16(dst, src, 16);
        }
        #pragma unroll
        for (int t = 0; t < BN * 4 / 256; t++) {      // B tile
            int idx = tid + t * 256;
            int row = idx >> 2, c = idx & 3;
            int gn = bn + row;
            const void* src = B + (long)(gn < N ? gn : 0) * ldb + k0 + c * 8;
            unsigned dst = sbase + (unsigned)(((stage * ROWS + BM + row) * RS + c * 8) * 2);
            cp16(dst, src, gn < N ? 16 : 0);
        }
        asm volatile("cp.async.commit_group;\n");
    };

    float acc[2][NT][4];
    #pragma unroll
    for (int mt = 0; mt < 2; mt++)
        #pragma unroll
        for (int nt = 0; nt < NT; nt++)
            #pragma unroll
            for (int r = 0; r < 4; r++) acc[mt][nt][r] = 0.f;

    int g = lane >> 2;
    int q = lane & 3;
    int ntiles = K / BK;

    auto compute = [&](int stage) {
        const bf16* As = sm + stage * ROWS * RS;
        const bf16* Bs = As + BM * RS;
        #pragma unroll
        for (int ks = 0; ks < BK; ks += 16) {
            unsigned a[2][4], b[NT][2];
            int ac = ks + q * 2;
            #pragma unroll
            for (int mt = 0; mt < 2; mt++) {
                int r = warpM + mt * 16 + g;
                a[mt][0] = *(const unsigned*)&As[r * RS + ac];
                a[mt][1] = *(const unsigned*)&As[(r + 8) * RS + ac];
                a[mt][2] = *(const unsigned*)&As[r * RS + ac + 8];
                a[mt][3] = *(const unsigned*)&As[(r + 8) * RS + ac + 8];
            }
            #pragma unroll
            for (int nt = 0; nt < NT; nt++) {
                int nr = warpN + nt * 8 + g;
                b[nt][0] = *(const unsigned*)&Bs[nr * RS + ac];
                b[nt][1] = *(const unsigned*)&Bs[nr * RS + ac + 8];
            }
            #pragma unroll
            for (int mt = 0; mt < 2; mt++)
                #pragma unroll
                for (int nt = 0; nt < NT; nt++)
                    MMA_BF16(acc[mt][nt], a[mt][0], a[mt][1], a[mt][2], a[mt][3],
                             b[nt][0], b[nt][1]);
        }
    };

    if (ST == 3) {
        issue(0, 0);
        issue(1, BK);
        for (int t = 0; t < ntiles; t++) {
            asm volatile("cp.async.wait_group 1;\n");
            __syncthreads();
            if (t + 2 < ntiles) issue((t + 2) % 3, (t + 2) * BK);
            compute(t % 3);
        }
    } else {   // ST == 2, double-sync double buffer
        issue(0, 0);
        for (int t = 0; t < ntiles; t++) {
            if (t + 1 < ntiles) {
                issue((t + 1) & 1, (t + 1) * BK);
                asm volatile("cp.async.wait_group 1;\n");
            } else {
                asm volatile("cp.async.wait_group 0;\n");
            }
            __syncthreads();
            compute(t & 1);
            __syncthreads();
        }
    }

    #pragma unroll
    for (int mt = 0; mt < 2; mt++) {
        int row0 = bm + warpM + mt * 16 + g;
        #pragma unroll
        for (int nt = 0; nt < NT; nt++) {
            int col = bn + warpN + nt * 8 + q * 2;
            if (col >= N) continue;
            float b0 = bias ? bias[col]     : 0.f;
            float b1 = bias ? bias[col + 1] : 0.f;
            float v00 = acc[mt][nt][0] + b0;
            float v01 = acc[mt][nt][1] + b1;
            float v10 = acc[mt][nt][2] + b0;
            float v11 = acc[mt][nt][3] + b1;
            if (do_relu) {
                v00 = fmaxf(v00, 0.f); v01 = fmaxf(v01, 0.f);
                v10 = fmaxf(v10, 0.f); v11 = fmaxf(v11, 0.f);
            }
            if (Cb) {
                *(unsigned*)(Cb + zoff + (long)row0 * ldc + col)       = packbf(v00, v01);
                *(unsigned*)(Cb + zoff + (long)(row0 + 8) * ldc + col) = packbf(v10, v11);
            } else {
                *(float2*)(C + zoff + (long)row0 * ldc + col)       = make_float2(v00, v01);
                *(float2*)(C + zoff + (long)(row0 + 8) * ldc + col) = make_float2(v10, v11);
            }
        }
    }
}

// ---------------- fused flash attention (bf16 qkv in, bf16 out) ----------------
// Register-staged K/V double buffering: prefetch next tile while computing current.
__global__ __launch_bounds__(256)
void flash_attn(const bf16* __restrict__ qkv, bf16* __restrict__ o) {
    constexpr int BM = 128, BN = 64, D = HD_, PD = 8;
    __shared__ __align__(16) bf16 Qs[BM][D + PD];
    __shared__ __align__(16) bf16 Ks[BN][D + PD];
    __shared__ __align__(16) bf16 Vs[D][BN + PD];

    int h  = blockIdx.y;
    int bm = blockIdx.x * BM;
    int tid = threadIdx.x;
    int lane = tid & 31;
    int w = tid >> 5;
    int g = lane >> 2;
    int q = lane & 3;

    const bf16* Qp = qkv + h * HD_;
    const bf16* Kp = qkv + H_ + h * HD_;
    const bf16* Vp = qkv + 2 * H_ + h * HD_;

    // per-thread K/V staging coords: 2 uint4 each
    int skey[2], sc[2];
    #pragma unroll
    for (int i = 0; i < 2; i++) {
        int idx = tid + i * 256;
        skey[i] = idx >> 3;
        sc[i]   = idx & 7;
    }

    // Q tile
    #pragma unroll
    for (int i = 0; i < 4; i++) {
        int idx = tid + i * 256;
        int row = idx >> 3;
        int c   = idx & 7;
        uint4 v = *(const uint4*)(Qp + (long)(bm + row) * (3 * H_) + c * 8);
        *(uint4*)&Qs[row][c * 8] = v;
    }

    float m0 = -1e30f, m1 = -1e30f, l0 = 0.f, l1 = 0.f;
    float out[8][4];
    #pragma unroll
    for (int ot = 0; ot < 8; ot++)
        #pragma unroll
        for (int r = 0; r < 4; r++) out[ot][r] = 0.f;

    int rowA = w * 16 + g;

    // prologue: load tile 0 into regs
    uint4 kreg[2], vreg[2];
    #pragma unroll
    for (int i = 0; i < 2; i++) {
        kreg[i] = *(const uint4*)(Kp + (long)skey[i] * (3 * H_) + sc[i] * 8);
        vreg[i] = *(const uint4*)(Vp + (long)skey[i] * (3 * H_) + sc[i] * 8);
    }

    for (int j = 0; j < S_ / BN; j++) {
        __syncthreads();   // previous compute done reading Ks/Vs
        #pragma unroll
        for (int i = 0; i < 2; i++) {
            *(uint4*)&Ks[skey[i]][sc[i] * 8] = kreg[i];
            __nv_bfloat162 p0 = *(__nv_bfloat162*)&vreg[i].x;
            __nv_bfloat162 p1 = *(__nv_bfloat162*)&vreg[i].y;
            __nv_bfloat162 p2 = *(__nv_bfloat162*)&vreg[i].z;
            __nv_bfloat162 p3 = *(__nv_bfloat162*)&vreg[i].w;
            int d0 = sc[i] * 8;
            int key = skey[i];
            Vs[d0 + 0][key] = p0.x; Vs[d0 + 1][key] = p0.y;
            Vs[d0 + 2][key] = p1.x; Vs[d0 + 3][key] = p1.y;
            Vs[d0 + 4][key] = p2.x; Vs[d0 + 5][key] = p2.y;
            Vs[d0 + 6][key] = p3.x; Vs[d0 + 7][key] = p3.y;
        }
        __syncthreads();

        // prefetch next tile while computing this one
        if (j + 1 < S_ / BN) {
            long base = (long)(j + 1) * BN;
            #pragma unroll
            for (int i = 0; i < 2; i++) {
                kreg[i] = *(const uint4*)(Kp + (base + skey[i]) * (3 * H_) + sc[i] * 8);
                vreg[i] = *(const uint4*)(Vp + (base + skey[i]) * (3 * H_) + sc[i] * 8);
            }
        }

        float acc[8][4];
        #pragma unroll
        for (int nt = 0; nt < 8; nt++)
            #pragma unroll
            for (int r = 0; r < 4; r++) acc[nt][r] = 0.f;
        #pragma unroll
        for (int kc = 0; kc < 4; kc++) {
            int ac = kc * 16 + q * 2;
            unsigned a0 = *(const unsigned*)&Qs[rowA][ac];
            unsigned a1 = *(const unsigned*)&Qs[rowA + 8][ac];
            unsigned a2 = *(const unsigned*)&Qs[rowA][ac + 8];
            unsigned a3 = *(const unsigned*)&Qs[rowA + 8][ac + 8];
            #pragma unroll
            for (int nt = 0; nt < 8; nt++) {
                unsigned b0 = *(const unsigned*)&Ks[nt * 8 + g][ac];
                unsigned b1 = *(const unsigned*)&Ks[nt * 8 + g][ac + 8];
                MMA_BF16(acc[nt], a0, a1, a2, a3, b0, b1);
            }
        }

        float tm0 = -1e30f, tm1 = -1e30f;
        #pragma unroll
        for (int nt = 0; nt < 8; nt++) {
            acc[nt][0] *= SCALE_; acc[nt][1] *= SCALE_;
            acc[nt][2] *= SCALE_; acc[nt][3] *= SCALE_;
            tm0 = fmaxf(tm0, fmaxf(acc[nt][0], acc[nt][1]));
            tm1 = fmaxf(tm1, fmaxf(acc[nt][2], acc[nt][3]));
        }
        tm0 = fmaxf(tm0, __shfl_xor_sync(0xffffffffu, tm0, 1));
        tm0 = fmaxf(tm0, __shfl_xor_sync(0xffffffffu, tm0, 2));
        tm1 = fmaxf(tm1, __shfl_xor_sync(0xffffffffu, tm1, 1));
        tm1 = fmaxf(tm1, __shfl_xor_sync(0xffffffffu, tm1, 2));
        float mn0 = fmaxf(m0, tm0), mn1 = fmaxf(m1, tm1);
        float corr0 = __expf(m0 - mn0), corr1 = __expf(m1 - mn1);
        float s0 = 0.f, s1 = 0.f;
        #pragma unroll
        for (int nt = 0; nt < 8; nt++) {
            acc[nt][0] = __expf(acc[nt][0] - mn0);
            acc[nt][1] = __expf(acc[nt][1] - mn0);
            acc[nt][2] = __expf(acc[nt][2] - mn1);
            acc[nt][3] = __expf(acc[nt][3] - mn1);
            s0 += acc[nt][0] + acc[nt][1];
            s1 += acc[nt][2] + acc[nt][3];
        }
        m0 = mn0; m1 = mn1;
        l0 = l0 * corr0 + s0;
        l1 = l1 * corr1 + s1;
        #pragma unroll
        for (int ot = 0; ot < 8; ot++) {
            out[ot][0] *= corr0; out[ot][1] *= corr0;
            out[ot][2] *= corr1; out[ot][3] *= corr1;
        }

        #pragma unroll
        for (int kc = 0; kc < 4; kc++) {
            unsigned a0 = packbf(acc[2 * kc][0],     acc[2 * kc][1]);
            unsigned a1 = packbf(acc[2 * kc][2],     acc[2 * kc][3]);
            unsigned a2 = packbf(acc[2 * kc + 1][0], acc[2 * kc + 1][1]);
            unsigned a3 = packbf(acc[2 * kc + 1][2], acc[2 * kc + 1][3]);
            int kb = kc * 16 + q * 2;
            #pragma unroll
            for (int ot = 0; ot < 8; ot++) {
                unsigned b0 = *(const unsigned*)&Vs[ot * 8 + g][kb];
                unsigned b1 = *(const unsigned*)&Vs[ot * 8 + g][kb + 8];
                MMA_BF16(out[ot], a0, a1, a2, a3, b0, b1);
            }
        }
    }

    l0 += __shfl_xor_sync(0xffffffffu, l0, 1);
    l0 += __shfl_xor_sync(0xffffffffu, l0, 2);
    l1 += __shfl_xor_sync(0xffffffffu, l1, 1);
    l1 += __shfl_xor_sync(0xffffffffu, l1, 2);
    float inv0 = 1.f / l0, inv1 = 1.f / l1;
    int row0 = bm + w * 16 + g;
    #pragma unroll
    for (int ot = 0; ot < 8; ot++) {
        int col = h * HD_ + ot * 8 + q * 2;
        *(unsigned*)(o + (long)row0 * H_ + col) =
            packbf(out[ot][0] * inv0, out[ot][1] * inv0);
        *(unsigned*)(o + (long)(row0 + 8) * H_ + col) =
            packbf(out[ot][2] * inv1, out[ot][3] * inv1);
    }
}

// ---------------- residual add + LayerNorm (dual write) ----------------
__global__ void ln_kernel(float* __restrict__ h, const float* __restrict__ t,
                          const float* __restrict__ g, const float* __restrict__ b,
                          bf16* __restrict__ hb) {
    __shared__ float red[H_];
    int s = blockIdx.x;
    int d = threadIdx.x;
    float v = h[s * H_ + d] + t[s * H_ + d];
    red[d] = v;
    __syncthreads();
    for (int o = H_ / 2; o > 0; o >>= 1) {
        if (d < o) red[d] += red[d + o];
        __syncthreads();
    }
    float m = red[0] * (1.f / H_);
    __syncthreads();
    float c = v - m;
    red[d] = c * c;
    __syncthreads();
    for (int o = H_ / 2; o > 0; o >>= 1) {
        if (d < o) red[d] += red[d + o];
        __syncthreads();
    }
    float var = red[0] * (1.f / H_);
    float r = c * rsqrtf(var + EPS_) * g[d] + b[d];
    h[s * H_ + d]  = r;
    hb[s * H_ + d] = __float2bfloat16_rn(r);
}

// ---------------- final log_softmax: bf16 logits in, fp32 out ----------------
__global__ void logsoftmax_kernel(const bf16* __restrict__ logits, float* __restrict__ out) {
    __shared__ float red[256];
    const bf16* p = logits + (long)blockIdx.x * V_;
    float* po = out + (long)blockIdx.x * V_;
    int t = threadIdx.x;
    float loc[40];
    float m = -1e30f;
    #pragma unroll
    for (int i = 0; i < 40; i++) {
        int c = t + i * 256;
        loc[i] = (c < V_) ? __bfloat162float(p[c]) : -1e30f;
        m = fmaxf(m, loc[i]);
    }
    red[t] = m;
    __syncthreads();
    for (int o = 128; o > 0; o >>= 1) {
        if (t < o) red[t] = fmaxf(red[t], red[t + o]);
        __syncthreads();
    }
    m = red[0];
    __syncthreads();
    float sum = 0.f;
    #pragma unroll
    for (int i = 0; i < 40; i++) {
        int c = t + i * 256;
        if (c < V_) sum += expf(loc[i] - m);
    }
    red[t] = sum;
    __syncthreads();
    for (int o = 128; o > 0; o >>= 1) {
        if (t < o) red[t] += red[t + o];
        __syncthreads();
    }
    float lse = m + logf(red[0]);
    #pragma unroll
    for (int i = 0; i < 40; i++) {
        int c = t + i * 256;
        if (c < V_) po[c] = loc[i] - lse;
    }
}

// ---------------- host side ----------------
static inline void gemm(const bf16* A, const bf16* B, const float* bias,
                        float* C, bf16* Cb,
                        int M, int N, int K, int lda, int ldb, int ldc,
                        int relu,
                        int Z = 1, long batchC = 0,
                        const int* sel = nullptr, long selStride = 0) {
    if (N >= 768) {
        dim3 grid((N + 127) / 128, M / 128, Z);
        gemm_bf<128, 2><<<grid, 256>>>(A, B, bias, C, Cb, M, N, K, lda, ldb, ldc,
                                       batchC, relu, sel, selStride);
    } else {
        dim3 grid((N + 63) / 64, M / 128, Z);
        gemm_bf<64, 3><<<grid, 256>>>(A, B, bias, C, Cb, M, N, K, lda, ldb, ldc,
                                      batchC, relu, sel, selStride);
    }
}

static inline void f2bf(const float* s, bf16* d, int n) {
    f2bf_kernel<<<(n / 4 + 255) / 256, 256>>>(s, d, n);
}

extern "C" void kernel_launch(void* const* d_in, const int* in_sizes, int n_in,
                              void* d_out, int out_size) {
    const int*   x         = (const int*)d_in[0];
    const float* emb       = (const float*)d_in[1];
    const float* moe_gw[3] = { (const float*)d_in[2], (const float*)d_in[6], (const float*)d_in[10] };
    const float* moe_gb[3] = { (const float*)d_in[3], (const float*)d_in[7], (const float*)d_in[11] };
    const float* moe_ew[3] = { (const float*)d_in[4], (const float*)d_in[8], (const float*)d_in[12] };
    const float* moe_eb[3] = { (const float*)d_in[5], (const float*)d_in[9], (const float*)d_in[13] };
    const float* attn_in_w  = (const float*)d_in[14];
    const float* attn_in_b  = (const float*)d_in[15];
    const float* attn_out_w = (const float*)d_in[16];
    const float* attn_out_b = (const float*)d_in[17];
    const float* ln1_g = (const float*)d_in[18];
    const float* ln1_b = (const float*)d_in[19];
    const float* ln2_g = (const float*)d_in[20];
    const float* ln2_b = (const float*)d_in[21];
    const float* ff1_w = (const float*)d_in[22];
    const float* ff1_b = (const float*)d_in[23];
    const float* ff2_w = (const float*)d_in[24];
    const float* ff2_b = (const float*)d_in[25];
    const float* fc_w  = (const float*)d_in[26];
    const float* fc_b  = (const float*)d_in[27];
    const float* out_w = (const float*)d_in[28];
    const float* out_b = (const float*)d_in[29];
    float* out = (float*)d_out;

    float *hbuf, *ybuf, *e0, *vals;
    int* sel;
    bf16 *hbf, *ybf, *qkvbf, *abf, *ffbf, *fcbf, *logbf;
    bf16 *w_ain, *w_aout, *w_ff1, *w_ff2, *w_fc, *w_out, *w_m0, *w_m1, *w_m2;
    cudaGetSymbolAddress((void**)&hbuf, g_h);
    cudaGetSymbolAddress((void**)&ybuf, g_y);
    cudaGetSymbolAddress((void**)&e0,   g_e0);
    cudaGetSymbolAddress((void**)&vals, g_vals);
    cudaGetSymbolAddress((void**)&sel,  g_sel);
    cudaGetSymbolAddress((void**)&hbf,   g_hbf);
    cudaGetSymbolAddress((void**)&ybf,   g_ybf);
    cudaGetSymbolAddress((void**)&qkvbf, g_qkvbf);
    cudaGetSymbolAddress((void**)&abf,   g_abf);
    cudaGetSymbolAddress((void**)&ffbf,  g_ffbf);
    cudaGetSymbolAddress((void**)&fcbf,  g_fcbf);
    cudaGetSymbolAddress((void**)&logbf, g_logbf);
    cudaGetSymbolAddress((void**)&w_ain,  g_w_attn_in);
    cudaGetSymbolAddress((void**)&w_aout, g_w_attn_out);
    cudaGetSymbolAddress((void**)&w_ff1,  g_w_ff1);
    cudaGetSymbolAddress((void**)&w_ff2,  g_w_ff2);
    cudaGetSymbolAddress((void**)&w_fc,   g_w_fc);
    cudaGetSymbolAddress((void**)&w_out,  g_w_out);
    cudaGetSymbolAddress((void**)&w_m0,   g_w_moe0);
    cudaGetSymbolAddress((void**)&w_m1,   g_w_moe1);
    cudaGetSymbolAddress((void**)&w_m2,   g_w_moe2);

    // 0) weight conversion (once per launch)
    f2bf(attn_in_w,  w_ain,  NL_ * 3 * H_ * H_);
    f2bf(attn_out_w, w_aout, NL_ * H_ * H_);
    f2bf(ff1_w,      w_ff1,  NL_ * FF_ * H_);
    f2bf(ff2_w,      w_ff2,  NL_ * H_ * FF_);
    f2bf(fc_w,       w_fc,   H_ * H_);
    f2bf(out_w,      w_out,  V_ * H_);
    f2bf(moe_ew[0],  w_m0,   NE_ * H_ * E_);
    f2bf(moe_ew[1],  w_m1,   NE_ * H_ * H_);
    f2bf(moe_ew[2],  w_m2,   NE_ * H_ * H_);

    // 1) embedding gather
    embed_kernel<<<S_, E_>>>(x, emb, hbuf, hbf);

    // 2) three MoE blocks; ping-pong (fp32 + bf16 views)
    const float* moe_in_f[3]  = { hbuf, ybuf, hbuf };
    const bf16*  moe_in_b[3]  = { hbf,  ybf,  hbf  };
    float*       moe_out_f[3] = { ybuf, hbuf, ybuf };
    bf16*        moe_out_b[3] = { ybf,  hbf,  ybf  };
    const bf16*  moe_w[3]     = { w_m0, w_m1, w_m2 };
    int          moe_din[3]   = { E_, H_, H_ };
    for (int i = 0; i < 3; i++) {
        int din = moe_din[i];
        gate_kernel<<<(S_ * 32) / 256, 256>>>(moe_in_f[i], din, moe_gw[i], moe_gb[i], vals, sel);
        gemm(moe_in_b[i], moe_w[i], nullptr, e0, nullptr, S_, H_, din, din, din, H_,
             0, 2, (long)S_ * H_, sel, (long)H_ * din);
        moe_combine<<<(S_ * H_) / 256, 256>>>(e0, e0 + (long)S_ * H_, moe_eb[i], vals, sel,
                                              moe_out_f[i], moe_out_b[i]);
    }
    float* cur  = ybuf;
    bf16*  curb = ybf;

    // 3) transformer layers
    for (int l = 0; l < NL_; l++) {
        gemm(curb, w_ain + (long)l * 3 * H_ * H_, attn_in_b + (long)l * 3 * H_,
             nullptr, qkvbf, S_, 3 * H_, H_, H_, H_, 3 * H_, 0);
        flash_attn<<<dim3(S_ / 128, NH_), 256>>>(qkvbf, abf);
        gemm(abf, w_aout + (long)l * H_ * H_, attn_out_b + (long)l * H_,
             e0, nullptr, S_, H_, H_, H_, H_, H_, 0);
        ln_kernel<<<S_, H_>>>(cur, e0, ln1_g + l * H_, ln1_b + l * H_, curb);
        gemm(curb, w_ff1 + (long)l * FF_ * H_, ff1_b + (long)l * FF_,
             nullptr, ffbf, S_, FF_, H_, H_, H_, FF_, 1);
        gemm(ffbf, w_ff2 + (long)l * H_ * FF_, ff2_b + (long)l * H_,
             e0, nullptr, S_, H_, FF_, FF_, FF_, H_, 0);
        ln_kernel<<<S_, H_>>>(cur, e0, ln2_g + l * H_, ln2_b + l * H_, curb);
    }

    // 4) fc + vocab logits (bf16) + log_softmax (bf16 -> fp32 out)
    gemm(curb, w_fc, fc_b, nullptr, fcbf, S_, H_, H_, H_, H_, H_, 0);
    gemm(fcbf, w_out, out_b, nullptr, logbf, S_, V_, H_, H_, H_, V_, 0);
    logsoftmax_kernel<<<S_, 256>>>(logbf, out);
}